// round 7
// baseline (speedup 1.0000x reference)
#include <cuda_runtime.h>
#include <cuda_bf16.h>
#include <math.h>
#include <stdint.h>

#define L     4
#define H     512
#define BATCH 32
#define TT    1024
#define G4    2048
#define LH    2048
#define JTOT  8192
#define NCTA  128
#define NTHR  512

#define SWZ(o) ((unsigned)(o) ^ (((unsigned)(o) >> 3) & 0x70u))

// ---- PTX helpers (base-target features only) ----
__device__ __forceinline__ uint32_t smem_u32(const void* p) {
    uint32_t a;
    asm("{ .reg .u64 t; cvta.to.shared.u64 t, %1; cvt.u32.u64 %0, t; }" : "=r"(a) : "l"(p));
    return a;
}
__device__ __forceinline__ void cp16(uint32_t dst, const void* src) {
    asm volatile("cp.async.cg.shared.global [%0], [%1], 16;" :: "r"(dst), "l"(src) : "memory");
}
#define CP_COMMIT() asm volatile("cp.async.commit_group;" ::: "memory")
#define CP_WAIT(n)  asm volatile("cp.async.wait_group %0;" :: "n"(n) : "memory")

__device__ __forceinline__ void ldsm_x4(uint32_t* r, uint32_t addr) {
    asm volatile("ldmatrix.sync.aligned.m8n8.x4.shared.b16 {%0,%1,%2,%3}, [%4];"
        : "=r"(r[0]), "=r"(r[1]), "=r"(r[2]), "=r"(r[3]) : "r"(addr));
}
__device__ __forceinline__ void mma_bf16(float* d, const uint32_t* a, uint32_t b0, uint32_t b1) {
    asm volatile("mma.sync.aligned.m16n8k16.row.col.f32.bf16.bf16.f32 "
        "{%0,%1,%2,%3}, {%4,%5,%6,%7}, {%8,%9}, {%0,%1,%2,%3};"
        : "+f"(d[0]), "+f"(d[1]), "+f"(d[2]), "+f"(d[3])
        : "r"(a[0]), "r"(a[1]), "r"(a[2]), "r"(a[3]), "r"(b0), "r"(b1));
}
__device__ __forceinline__ void wait_cnt(const unsigned* p, unsigned target) {
    unsigned v;
    do {
        asm volatile("ld.acquire.gpu.u32 %0, [%1];" : "=r"(v) : "l"(p) : "memory");
    } while (v < target);
}
__device__ __forceinline__ float sigm(float x) { return 1.f / (1.f + __expf(-x)); }
__device__ __forceinline__ float tanh_f(float x) { return 1.f - 2.f / (1.f + __expf(2.f * x)); }

// ---- static device scratch ----
__device__ __align__(16) char g_Uimg[(size_t)128 * 16 * 2 * 16384];  // [c][chunk][hl] 16KB
__device__ __align__(16) char g_Wimg[(size_t)4 * 128 * 2 * 16384];   // [l][c][hl] 16KB
__device__ __align__(16) char g_xpimg[(size_t)TT * 2 * 32768];       // [t][hl] 32KB
__device__ __align__(16) char g_hinimg[(size_t)3 * 2 * 32768];       // [l][hl]
__device__ __align__(16) char g_hximg[2][(size_t)16 * 2 * 8192];     // [parity][chunk][hl]
__device__ float g_h[L][BATCH][H];
__device__ float g_c[L][BATCH][H];
__device__ float g_ugemm[2][BATCH][JTOT];                            // [parity]
__device__ unsigned g_cntA[4];
__device__ unsigned g_cntB[4];
__device__ unsigned g_cntC[4];

// ---- prep kernels ----
__global__ void prep_U_img(const float* __restrict__ U)
{
    int blk = blockIdx.x;                 // c*16 + chunk
    int c = blk >> 4, chunk = blk & 15;
    char* dsth = g_Uimg + ((size_t)blk * 2) * 16384;
    char* dstl = dsth + 16384;
    for (int i = threadIdx.x; i < 1024; i += 256) {
        int r = i >> 4, s8 = i & 15;
        const float* src = U + ((size_t)(c * 64 + r)) * LH + chunk * 128 + s8 * 8;
        __nv_bfloat16 hb[8], lb[8];
        #pragma unroll
        for (int j = 0; j < 8; ++j) {
            float v = src[j];
            hb[j] = __float2bfloat16(v);
            lb[j] = __float2bfloat16(v - __bfloat162float(hb[j]));
        }
        unsigned byte = SWZ((unsigned)((r >> 3) * 1024 + (s8 >> 3) * 8192 +
                                       (r & 7) * 128 + (s8 & 7) * 16));
        *(uint4*)(dsth + byte) = *(uint4*)hb;
        *(uint4*)(dstl + byte) = *(uint4*)lb;
    }
}

__global__ void prep_W_img(const float* __restrict__ W)
{
    int blk = blockIdx.x;                 // l*128 + c
    int l = blk >> 7, c = blk & 127;
    char* dsth = g_Wimg + ((size_t)blk * 2) * 16384;
    char* dstl = dsth + 16384;
    for (int i = threadIdx.x; i < 1024; i += 256) {
        int r = i >> 6, s8 = i & 63;
        int q = r >> 2, ms = r & 3;
        int wrow = q * 512 + c * 4 + ms;
        const float* src = W + ((size_t)(l * G4 + wrow)) * H + s8 * 8;
        __nv_bfloat16 hb[8], lb[8];
        #pragma unroll
        for (int j = 0; j < 8; ++j) {
            float v = src[j];
            hb[j] = __float2bfloat16(v);
            lb[j] = __float2bfloat16(v - __bfloat162float(hb[j]));
        }
        unsigned byte = SWZ((unsigned)((r >> 3) * 1024 + (s8 >> 3) * 2048 +
                                       (r & 7) * 128 + (s8 & 7) * 16));
        *(uint4*)(dsth + byte) = *(uint4*)hb;
        *(uint4*)(dstl + byte) = *(uint4*)lb;
    }
}

__global__ void xp_kernel(const float* __restrict__ x,
                          const float* __restrict__ lin_w,
                          const float* __restrict__ lin_b,
                          const float* __restrict__ mask_w)
{
    __shared__ float xs[16][128];
    int tb0 = blockIdx.x * 16;
    int tid = threadIdx.x;
    #pragma unroll
    for (int r = 0; r < 8; ++r) {
        int e = r * 256 + tid;
        xs[e >> 7][e & 127] = x[(size_t)(tb0 + (e >> 7)) * 128 + (e & 127)];
    }
    __syncthreads();
    int h0 = tid, h1 = tid + 256;
    const float* w0 = lin_w + (size_t)h0 * 128;
    const float* w1 = lin_w + (size_t)h1 * 128;
    float acc0[16], acc1[16];
    #pragma unroll
    for (int p = 0; p < 16; ++p) { acc0[p] = 0.f; acc1[p] = 0.f; }
    for (int i = 0; i < 128; i += 4) {
        float4 a = *(const float4*)(w0 + i);
        float4 b = *(const float4*)(w1 + i);
        #pragma unroll
        for (int p = 0; p < 16; ++p) {
            float4 xv = *(const float4*)&xs[p][i];
            acc0[p] += a.x * xv.x + a.y * xv.y + a.z * xv.z + a.w * xv.w;
            acc1[p] += b.x * xv.x + b.y * xv.y + b.z * xv.z + b.w * xv.w;
        }
    }
    float b0 = lin_b[h0], b1 = lin_b[h1];
    #pragma unroll
    for (int p = 0; p < 16; ++p) {
        int tb = tb0 + p;
        int tt = tb >> 5, bb = tb & 31;
        char* base = g_xpimg + (size_t)tt * 65536;
        #pragma unroll
        for (int cc = 0; cc < 2; ++cc) {
            int hh = cc ? h1 : h0;
            float v = ((cc ? acc1[p] : acc0[p]) + (cc ? b1 : b0)) *
                      mask_w[(size_t)bb * H + hh];
            __nv_bfloat16 hb = __float2bfloat16(v);
            __nv_bfloat16 lb = __float2bfloat16(v - __bfloat162float(hb));
            int seg = hh >> 3;
            unsigned byte = SWZ((unsigned)((bb >> 3) * 1024 + (seg >> 3) * 4096 +
                                           (bb & 7) * 128 + (seg & 7) * 16 + (hh & 7) * 2));
            *(__nv_bfloat16*)(base + byte) = hb;
            *(__nv_bfloat16*)(base + 32768 + byte) = lb;
        }
    }
}

__global__ void init_hc(const float* __restrict__ h0, const float* __restrict__ c0)
{
    if (blockIdx.x == 0 && threadIdx.x < 4) {
        g_cntA[threadIdx.x] = 0;
        g_cntB[threadIdx.x] = 0;
        g_cntC[threadIdx.x] = 0;
    }
    float* hp = &g_h[0][0][0];
    float* cp = &g_c[0][0][0];
    for (int i = blockIdx.x * blockDim.x + threadIdx.x; i < L * BATCH * H;
         i += gridDim.x * blockDim.x)
        { hp[i] = h0[i]; cp[i] = c0[i]; }
}

// ---- persistent kernel ----
// dyn SMEM union: B: Ubuf 2x32K @0, hxbuf 2x16K @65536 | C: inp 64K @0, W 2x32K @65536
#define SMEM_DYN (131072 + 1024)

__global__ void __launch_bounds__(NTHR, 1)
rnn_kernel(const float* __restrict__ G,
           const float* __restrict__ mask_u,
           const float* __restrict__ mask_w,
           float* __restrict__ out)
{
    extern __shared__ char smc_raw[];
    __shared__ float redA[16];
    __shared__ float ghA;
    __shared__ float sm_g[16][33];
    __shared__ float red[4][16][33];

    const int c    = blockIdx.x;
    const int tid  = threadIdx.x;
    const int wid  = tid >> 5;
    const int lane = tid & 31;

    uint32_t sbr = smem_u32(smc_raw);
    uint32_t sb  = (sbr + 1023u) & ~1023u;

    // A: CTA = (layer, batch)
    const int al  = c & 3;
    const int abt = c >> 2;
    // B: warp = 4 J strips x 4 batch strips; CTA's J layer group:
    const int rs = wid >> 2;
    const int cs = wid & 3;
    const int jlay = c >> 5;                 // layer owning this CTA's J rows
    // C: warp = (K split, batch strip); thread = (row r16, batch cb)
    const int ks = wid >> 2;
    const int ns = wid & 3;
    const int cb   = wid * 2 + (lane & 1);
    const int r16  = lane >> 1;
    const int q    = r16 >> 2;
    const int ms   = r16 & 3;
    const int mg   = c * 4 + ms;
    const int crow = q * 512 + mg;

    float* out_h = out;
    float* out_c = out + L * BATCH * H;
    float* out_g = out + 2 * L * BATCH * H;

    for (int t = 0; t < TT; ++t) {
        const int par = t & 1;
        const unsigned tA = 32u * (unsigned)(t + 1);
        const unsigned tB = 32u * (unsigned)(t + 1);
        const unsigned tC = 128u * (unsigned)(t + 1);

        // ===== A: hx build for (al, abt); waits only its own layer's C(t-1) =====
        {
            wait_cnt(&g_cntC[al], 128u * (unsigned)t);
            float hm = g_h[al][abt][tid] * mask_u[((size_t)(al * BATCH + abt)) * H + tid];
            float s  = hm * G[al * H + tid];
            #pragma unroll
            for (int o = 16; o; o >>= 1) s += __shfl_xor_sync(~0u, s, o);
            if (lane == 0) redA[wid] = s;
            __syncthreads();
            if (tid == 0) {
                float ss = 0.f;
                #pragma unroll
                for (int r = 0; r < 16; ++r) ss += redA[r];
                float gh = sigm(ss);
                ghA = gh;
                out_g[(size_t)(al * BATCH + abt) * TT + t] = gh;
            }
            __syncthreads();
            float v = ghA * hm;
            __nv_bfloat16 hb = __float2bfloat16(v);
            __nv_bfloat16 lb = __float2bfloat16(v - __bfloat162float(hb));
            int kg = al * 512 + tid;
            int chunk = kg >> 7, kl = kg & 127, seg = kl >> 3;
            unsigned byte = SWZ((unsigned)((abt >> 3) * 1024 + (seg >> 3) * 4096 +
                                           (abt & 7) * 128 + (seg & 7) * 16 + (kl & 7) * 2));
            char* base = g_hximg[par] + (size_t)chunk * 16384;
            *(__nv_bfloat16*)(base + byte) = hb;
            *(__nv_bfloat16*)(base + 8192 + byte) = lb;
            __syncthreads();
            if (tid == 0) {
                __threadfence();
                atomicAdd(&g_cntA[al], 1u);
            }
        }

        // ===== B: U-GEMM (bf16x3), D[64 J x 32 B], K=2048, chunks of 128 =====
        {
            float d[4] = {0.f, 0.f, 0.f, 0.f};
            auto stageB = [&](int ck) {
                int buf = ck & 1;
                const char* us = g_Uimg + ((size_t)(c * 16 + ck) * 2) * 16384;
                #pragma unroll
                for (int i = 0; i < 4; ++i) {
                    int idx = i * 512 + tid;
                    cp16(sb + buf * 32768 + idx * 16, us + idx * 16);
                }
                const char* hs = g_hximg[par] + (size_t)ck * 2 * 8192;
                #pragma unroll
                for (int i = 0; i < 2; ++i) {
                    int idx = i * 512 + tid;
                    cp16(sb + 65536 + buf * 16384 + idx * 16, hs + idx * 16);
                }
            };

            wait_cnt(&g_cntA[0], tA);
            stageB(0);
            CP_COMMIT();
            for (int ck = 0; ck < 16; ++ck) {
                if (ck < 15) {
                    if (((ck + 1) & 3) == 0) wait_cnt(&g_cntA[(ck + 1) >> 2], tA);
                    stageB(ck + 1);
                    CP_COMMIT();
                    CP_WAIT(1);
                } else {
                    CP_WAIT(0);
                }
                __syncthreads();

                uint32_t auh = sb + (ck & 1) * 32768, aul = auh + 16384;
                uint32_t buh = sb + 65536 + (ck & 1) * 16384, bul = buh + 8192;
                #pragma unroll
                for (int g = 0; g < 4; ++g) {
                    uint32_t baddr = (g >> 1) * 4096 + (cs * 8 + (lane & 7)) * 128 +
                                     (g & 1) * 64 + (lane >> 3) * 16;
                    uint32_t bh[4], bl_[4];
                    ldsm_x4(bh,  buh + SWZ(baddr));
                    ldsm_x4(bl_, bul + SWZ(baddr));
                    #pragma unroll
                    for (int sh = 0; sh < 2; ++sh) {
                        int s = g * 2 + sh;
                        uint32_t aaddr = (s >> 2) * 8192 + (rs * 16 + (lane & 15)) * 128 +
                                         (s & 3) * 32 + (lane >> 4) * 16;
                        uint32_t ah[4], al_[4];
                        ldsm_x4(ah,  auh + SWZ(aaddr));
                        ldsm_x4(al_, aul + SWZ(aaddr));
                        mma_bf16(d, ah,  bh[2 * sh],  bh[2 * sh + 1]);
                        mma_bf16(d, ah,  bl_[2 * sh], bl_[2 * sh + 1]);
                        mma_bf16(d, al_, bh[2 * sh],  bh[2 * sh + 1]);
                    }
                }
                __syncthreads();
            }
            int m = c * 64 + rs * 16 + (lane >> 2);
            int n = cs * 8 + (lane & 3) * 2;
            g_ugemm[par][n][m]         = d[0];
            g_ugemm[par][n + 1][m]     = d[1];
            g_ugemm[par][n][m + 8]     = d[2];
            g_ugemm[par][n + 1][m + 8] = d[3];
            __syncthreads();
            if (tid == 0) {
                __threadfence();
                atomicAdd(&g_cntB[jlay], 1u);
            }
        }

        // ===== C: serial layer chain (counter-gated, no grid barrier) =====
        #pragma unroll
        for (int l = 0; l < 4; ++l) {
            if (l > 0) wait_cnt(&g_cntC[l - 1], tC);
            const char* isrc = (l == 0) ? (g_xpimg + (size_t)t * 65536)
                                        : (g_hinimg + (size_t)(l - 1) * 65536);
            #pragma unroll
            for (int i = 0; i < 8; ++i) {
                int idx = i * 512 + tid;
                cp16(sb + idx * 16, isrc + idx * 16);
            }
            if (l == 0) {
                const char* wsrc = g_Wimg + ((size_t)c * 2) * 16384;
                #pragma unroll
                for (int i = 0; i < 4; ++i) {
                    int idx = i * 512 + tid;
                    cp16(sb + 65536 + idx * 16, wsrc + idx * 16);
                }
            }
            CP_COMMIT();
            if (l < 3) {
                const char* wsrc = g_Wimg + ((size_t)((l + 1) * 128 + c) * 2) * 16384;
                uint32_t wdst = sb + 65536 + ((l + 1) & 1) * 32768;
                #pragma unroll
                for (int i = 0; i < 4; ++i) {
                    int idx = i * 512 + tid;
                    cp16(wdst + idx * 16, wsrc + idx * 16);
                }
                CP_COMMIT();
                CP_WAIT(1);
            } else {
                CP_WAIT(0);
            }
            __syncthreads();

            wait_cnt(&g_cntB[l], tB);
            float ug = g_ugemm[par][cb][l * G4 + crow];

            float dd[4] = {0.f, 0.f, 0.f, 0.f};
            uint32_t wh = sb + 65536 + (l & 1) * 32768, wl = wh + 16384;
            uint32_t ih = sb, il = sb + 32768;
            #pragma unroll
            for (int gg = 0; gg < 4; ++gg) {
                uint32_t baddr = (ks * 2 + (gg >> 1)) * 4096 + (ns * 8 + (lane & 7)) * 128 +
                                 (gg & 1) * 64 + (lane >> 3) * 16;
                uint32_t bh[4], bl_[4];
                ldsm_x4(bh,  ih + SWZ(baddr));
                ldsm_x4(bl_, il + SWZ(baddr));
                #pragma unroll
                for (int jh = 0; jh < 2; ++jh) {
                    int s = ks * 8 + gg * 2 + jh;
                    uint32_t aaddr = (s >> 2) * 2048 + (lane & 15) * 128 +
                                     (s & 3) * 32 + (lane >> 4) * 16;
                    uint32_t ah[4], al_[4];
                    ldsm_x4(ah,  wh + SWZ(aaddr));
                    ldsm_x4(al_, wl + SWZ(aaddr));
                    mma_bf16(dd, ah,  bh[2 * jh],  bh[2 * jh + 1]);
                    mma_bf16(dd, ah,  bl_[2 * jh], bl_[2 * jh + 1]);
                    mma_bf16(dd, al_, bh[2 * jh],  bh[2 * jh + 1]);
                }
            }
            {
                int m0 = lane >> 2, n0 = ns * 8 + (lane & 3) * 2;
                red[ks][m0][n0]         = dd[0];
                red[ks][m0][n0 + 1]     = dd[1];
                red[ks][m0 + 8][n0]     = dd[2];
                red[ks][m0 + 8][n0 + 1] = dd[3];
            }
            __syncthreads();

            float a = red[0][r16][cb] + red[1][r16][cb] +
                      red[2][r16][cb] + red[3][r16][cb] + ug;
            float act = (q == 2) ? tanh_f(a) : sigm(a);
            sm_g[r16][cb] = act;
            __syncthreads();
            if (q == 0) {
                float gf  = sm_g[4 + ms][cb];
                float gg_ = sm_g[8 + ms][cb];
                float go  = sm_g[12 + ms][cb];
                float cold = g_c[l][cb][mg];
                float cn = gf * cold + act * gg_;
                float hy = go * tanh_f(cn);
                g_c[l][cb][mg] = cn;
                g_h[l][cb][mg] = hy;
                if (l < 3) {
                    float hv = hy * mask_w[((size_t)((l + 1) * BATCH + cb)) * H + mg];
                    __nv_bfloat16 hb = __float2bfloat16(hv);
                    __nv_bfloat16 lb = __float2bfloat16(hv - __bfloat162float(hb));
                    int seg = mg >> 3;
                    unsigned byte = SWZ((unsigned)((cb >> 3) * 1024 + (seg >> 3) * 4096 +
                                                   (cb & 7) * 128 + (seg & 7) * 16 + (mg & 7) * 2));
                    char* base = g_hinimg + (size_t)l * 65536;
                    *(__nv_bfloat16*)(base + byte) = hb;
                    *(__nv_bfloat16*)(base + 32768 + byte) = lb;
                }
            }
            __syncthreads();
            if (tid == 0) {
                __threadfence();
                atomicAdd(&g_cntC[l], 1u);
            }
        }
    }

    // final outputs: wait for all layers' last C, then copy
    wait_cnt(&g_cntC[0], 128u * TT);
    wait_cnt(&g_cntC[1], 128u * TT);
    wait_cnt(&g_cntC[2], 128u * TT);
    wait_cnt(&g_cntC[3], 128u * TT);
    const float* hp = &g_h[0][0][0];
    const float* cp = &g_c[0][0][0];
    for (int idx = c * NTHR + tid; idx < L * BATCH * H; idx += NCTA * NTHR) {
        out_h[idx] = hp[idx];
        out_c[idx] = cp[idx];
    }
}

// ---- launch ----
extern "C" void kernel_launch(void* const* d_in, const int* in_sizes, int n_in,
                              void* d_out, int out_size)
{
    const float* x      = (const float*)d_in[0];
    const float* lin_w  = (const float*)d_in[1];
    const float* lin_b  = (const float*)d_in[2];
    const float* W      = (const float*)d_in[3];
    const float* U      = (const float*)d_in[4];
    const float* G      = (const float*)d_in[5];
    const float* mask_u = (const float*)d_in[6];
    const float* mask_w = (const float*)d_in[7];
    const float* h0     = (const float*)d_in[8];
    const float* c0     = (const float*)d_in[9];
    float* out = (float*)d_out;
    (void)in_sizes; (void)n_in; (void)out_size;

    prep_U_img<<<128 * 16, 256>>>(U);
    prep_W_img<<<4 * 128, 256>>>(W);
    xp_kernel<<<(TT * BATCH) / 16, 256>>>(x, lin_w, lin_b, mask_w);
    init_hc<<<64, 256>>>(h0, c0);

    cudaFuncSetAttribute(rnn_kernel, cudaFuncAttributeMaxDynamicSharedMemorySize, SMEM_DYN);
    rnn_kernel<<<NCTA, NTHR, SMEM_DYN>>>(G, mask_u, mask_w, out);
}

// round 8
// speedup vs baseline: 1.0947x; 1.0947x over previous
#include <cuda_runtime.h>
#include <cuda_bf16.h>
#include <math.h>
#include <stdint.h>

#define L     4
#define H     512
#define BATCH 32
#define TT    1024
#define G4    2048
#define LH    2048
#define JTOT  8192
#define NCTA  128
#define NTHR  512

#define SWZ(o) ((unsigned)(o) ^ (((unsigned)(o) >> 3) & 0x70u))

// ---- PTX helpers (base-target features only) ----
__device__ __forceinline__ uint32_t smem_u32(const void* p) {
    uint32_t a;
    asm("{ .reg .u64 t; cvta.to.shared.u64 t, %1; cvt.u32.u64 %0, t; }" : "=r"(a) : "l"(p));
    return a;
}
__device__ __forceinline__ void cp16(uint32_t dst, const void* src) {
    asm volatile("cp.async.cg.shared.global [%0], [%1], 16;" :: "r"(dst), "l"(src) : "memory");
}
#define CP_COMMIT() asm volatile("cp.async.commit_group;" ::: "memory")
#define CP_WAIT(n)  asm volatile("cp.async.wait_group %0;" :: "n"(n) : "memory")

__device__ __forceinline__ void ldsm_x4(uint32_t* r, uint32_t addr) {
    asm volatile("ldmatrix.sync.aligned.m8n8.x4.shared.b16 {%0,%1,%2,%3}, [%4];"
        : "=r"(r[0]), "=r"(r[1]), "=r"(r[2]), "=r"(r[3]) : "r"(addr));
}
__device__ __forceinline__ void mma_bf16(float* d, const uint32_t* a, uint32_t b0, uint32_t b1) {
    asm volatile("mma.sync.aligned.m16n8k16.row.col.f32.bf16.bf16.f32 "
        "{%0,%1,%2,%3}, {%4,%5,%6,%7}, {%8,%9}, {%0,%1,%2,%3};"
        : "+f"(d[0]), "+f"(d[1]), "+f"(d[2]), "+f"(d[3])
        : "r"(a[0]), "r"(a[1]), "r"(a[2]), "r"(a[3]), "r"(b0), "r"(b1));
}
__device__ __forceinline__ float sigm(float x) { return 1.f / (1.f + __expf(-x)); }
__device__ __forceinline__ float tanh_f(float x) { return 1.f - 2.f / (1.f + __expf(2.f * x)); }

// ---- static device scratch ----
__device__ __align__(16) char g_Uimg[(size_t)128 * 16 * 2 * 16384];  // [c][chunk][hl] 16KB
__device__ __align__(16) char g_Wimg[(size_t)4 * 128 * 2 * 16384];   // [l][c][hl] 16KB
__device__ __align__(16) char g_xpimg[(size_t)TT * 2 * 32768];       // [t][hl] 32KB
__device__ __align__(16) char g_hinimg[(size_t)3 * 2 * 32768];       // [l][hl]
__device__ float g_hm[BATCH][LH];                                    // h*mask_u (fp32)
__device__ float g_gsum[2][4][BATCH];                                // gate-sum parity buffers
__device__ float g_h[L][BATCH][H];
__device__ float g_c[L][BATCH][H];
__device__ float g_ugemm[BATCH][JTOT];
__device__ unsigned g_cnt = 0;
__device__ unsigned g_gen = 0;

// ---- grid barrier: acq_rel arrive + acquire poll (no full membars) ----
__device__ __forceinline__ void grid_sync()
{
    __syncthreads();
    if (threadIdx.x == 0) {
        unsigned g;
        asm volatile("ld.relaxed.gpu.global.u32 %0, [%1];" : "=r"(g) : "l"(&g_gen));
        unsigned old;
        asm volatile("atom.acq_rel.gpu.global.add.u32 %0, [%1], %2;"
                     : "=r"(old) : "l"(&g_cnt), "r"(1u) : "memory");
        if (old == NCTA - 1u) {
            asm volatile("st.relaxed.gpu.global.u32 [%0], %1;" :: "l"(&g_cnt), "r"(0u) : "memory");
            asm volatile("st.release.gpu.global.u32 [%0], %1;" :: "l"(&g_gen), "r"(g + 1u) : "memory");
        } else {
            unsigned v;
            do {
                asm volatile("ld.acquire.gpu.global.u32 %0, [%1];" : "=r"(v) : "l"(&g_gen) : "memory");
            } while (v == g);
        }
    }
    __syncthreads();
}

// ---- prep kernels ----
__global__ void prep_U_img(const float* __restrict__ U)
{
    int blk = blockIdx.x;                 // c*16 + chunk
    int c = blk >> 4, chunk = blk & 15;
    char* dsth = g_Uimg + ((size_t)blk * 2) * 16384;
    char* dstl = dsth + 16384;
    for (int i = threadIdx.x; i < 1024; i += 256) {
        int r = i >> 4, s8 = i & 15;
        const float* src = U + ((size_t)(c * 64 + r)) * LH + chunk * 128 + s8 * 8;
        __nv_bfloat16 hb[8], lb[8];
        #pragma unroll
        for (int j = 0; j < 8; ++j) {
            float v = src[j];
            hb[j] = __float2bfloat16(v);
            lb[j] = __float2bfloat16(v - __bfloat162float(hb[j]));
        }
        unsigned byte = SWZ((unsigned)((r >> 3) * 1024 + (s8 >> 3) * 8192 +
                                       (r & 7) * 128 + (s8 & 7) * 16));
        *(uint4*)(dsth + byte) = *(uint4*)hb;
        *(uint4*)(dstl + byte) = *(uint4*)lb;
    }
}

__global__ void prep_W_img(const float* __restrict__ W)
{
    int blk = blockIdx.x;                 // l*128 + c
    int l = blk >> 7, c = blk & 127;
    char* dsth = g_Wimg + ((size_t)blk * 2) * 16384;
    char* dstl = dsth + 16384;
    for (int i = threadIdx.x; i < 1024; i += 256) {
        int r = i >> 6, s8 = i & 63;
        int q = r >> 2, ms = r & 3;
        int wrow = q * 512 + c * 4 + ms;
        const float* src = W + ((size_t)(l * G4 + wrow)) * H + s8 * 8;
        __nv_bfloat16 hb[8], lb[8];
        #pragma unroll
        for (int j = 0; j < 8; ++j) {
            float v = src[j];
            hb[j] = __float2bfloat16(v);
            lb[j] = __float2bfloat16(v - __bfloat162float(hb[j]));
        }
        unsigned byte = SWZ((unsigned)((r >> 3) * 1024 + (s8 >> 3) * 2048 +
                                       (r & 7) * 128 + (s8 & 7) * 16));
        *(uint4*)(dsth + byte) = *(uint4*)hb;
        *(uint4*)(dstl + byte) = *(uint4*)lb;
    }
}

__global__ void xp_kernel(const float* __restrict__ x,
                          const float* __restrict__ lin_w,
                          const float* __restrict__ lin_b,
                          const float* __restrict__ mask_w)
{
    __shared__ float xs[16][128];
    int tb0 = blockIdx.x * 16;
    int tid = threadIdx.x;
    #pragma unroll
    for (int r = 0; r < 8; ++r) {
        int e = r * 256 + tid;
        xs[e >> 7][e & 127] = x[(size_t)(tb0 + (e >> 7)) * 128 + (e & 127)];
    }
    __syncthreads();
    int h0 = tid, h1 = tid + 256;
    const float* w0 = lin_w + (size_t)h0 * 128;
    const float* w1 = lin_w + (size_t)h1 * 128;
    float acc0[16], acc1[16];
    #pragma unroll
    for (int p = 0; p < 16; ++p) { acc0[p] = 0.f; acc1[p] = 0.f; }
    for (int i = 0; i < 128; i += 4) {
        float4 a = *(const float4*)(w0 + i);
        float4 b = *(const float4*)(w1 + i);
        #pragma unroll
        for (int p = 0; p < 16; ++p) {
            float4 xv = *(const float4*)&xs[p][i];
            acc0[p] += a.x * xv.x + a.y * xv.y + a.z * xv.z + a.w * xv.w;
            acc1[p] += b.x * xv.x + b.y * xv.y + b.z * xv.z + b.w * xv.w;
        }
    }
    float b0 = lin_b[h0], b1 = lin_b[h1];
    #pragma unroll
    for (int p = 0; p < 16; ++p) {
        int tb = tb0 + p;
        int tt = tb >> 5, bb = tb & 31;
        char* base = g_xpimg + (size_t)tt * 65536;
        #pragma unroll
        for (int cc = 0; cc < 2; ++cc) {
            int hh = cc ? h1 : h0;
            float v = ((cc ? acc1[p] : acc0[p]) + (cc ? b1 : b0)) *
                      mask_w[(size_t)bb * H + hh];
            __nv_bfloat16 hb = __float2bfloat16(v);
            __nv_bfloat16 lb = __float2bfloat16(v - __bfloat162float(hb));
            int seg = hh >> 3;
            unsigned byte = SWZ((unsigned)((bb >> 3) * 1024 + (seg >> 3) * 4096 +
                                           (bb & 7) * 128 + (seg & 7) * 16 + (hh & 7) * 2));
            *(__nv_bfloat16*)(base + byte) = hb;
            *(__nv_bfloat16*)(base + 32768 + byte) = lb;
        }
    }
}

__global__ void reset_gsum()
{
    if (threadIdx.x < 256) ((float*)g_gsum)[threadIdx.x] = 0.f;
}

// init h/c state, hm = h0*mask_u, gsum[0] = sum hm*G
__global__ void init_hc(const float* __restrict__ h0, const float* __restrict__ c0,
                        const float* __restrict__ mask_u, const float* __restrict__ G)
{
    for (int i = blockIdx.x * blockDim.x + threadIdx.x; i < L * BATCH * H;
         i += gridDim.x * blockDim.x) {
        (&g_h[0][0][0])[i] = h0[i];
        (&g_c[0][0][0])[i] = c0[i];
        int l = i >> 14, b = (i >> 9) & 31, k = i & 511;
        float hm = h0[i] * mask_u[i];
        g_hm[b][l * 512 + k] = hm;
        atomicAdd(&g_gsum[0][l][b], hm * G[l * H + k]);
    }
}

// ---- persistent kernel ----
// dyn SMEM union: B: Ubuf 2x32K @0, hxbuf 2x16K @65536 | C: inp 64K @0, W 2x32K @65536
#define SMEM_DYN (131072 + 1024)

__global__ void __launch_bounds__(NTHR, 1)
rnn_kernel(const float* __restrict__ G,
           const float* __restrict__ mask_u,
           const float* __restrict__ mask_w,
           float* __restrict__ out)
{
    extern __shared__ char smc_raw[];
    __shared__ float sm_g[16][33];
    __shared__ float red[4][16][33];
    __shared__ float gh_s[4][32];

    const int c    = blockIdx.x;
    const int tid  = threadIdx.x;
    const int wid  = tid >> 5;
    const int lane = tid & 31;

    uint32_t sbr = smem_u32(smc_raw);
    uint32_t sb  = (sbr + 1023u) & ~1023u;
    char* smc = smc_raw + (sb - sbr);

    // out_g role: CTA = (layer, batch)
    const int al  = c & 3;
    const int abt = c >> 2;
    // B: warp = 4 J strips x 4 batch strips
    const int rs = wid >> 2;
    const int cs = wid & 3;
    // hx staging identity
    const int hb_b  = tid >> 4;              // batch 0..31
    const int hb_sg = tid & 15;              // k segment (8 elems)
    // C: warp = (K split, batch strip); thread = (row r16, batch cb)
    const int ks = wid >> 2;
    const int ns = wid & 3;
    const int cb   = wid * 2 + (lane & 1);
    const int r16  = lane >> 1;
    const int q    = r16 >> 2;
    const int ms   = r16 & 3;
    const int mg   = c * 4 + ms;
    const int crow = q * 512 + mg;

    // per-thread constants for C cell update
    float Gv[4], muv[4], mwv[3];
    #pragma unroll
    for (int l = 0; l < 4; ++l) {
        Gv[l]  = G[l * H + mg];
        muv[l] = mask_u[((size_t)(l * BATCH + cb)) * H + mg];
    }
    #pragma unroll
    for (int l = 0; l < 3; ++l)
        mwv[l] = mask_w[((size_t)((l + 1) * BATCH + cb)) * H + mg];

    float* out_h = out;
    float* out_c = out + L * BATCH * H;
    float* out_g = out + 2 * L * BATCH * H;

    for (int t = 0; t < TT; ++t) {
        const int par = t & 1;

        // ===== B: gh from gsum, then U-GEMM (bf16x3), D[64 J x 32 B] =====
        {
            if (tid < 128) gh_s[tid >> 5][tid & 31] = sigm(g_gsum[par][tid >> 5][tid & 31]);
            __syncthreads();
            if (tid == 0) out_g[(size_t)(al * BATCH + abt) * TT + t] = gh_s[al][abt];

            float d[4] = {0.f, 0.f, 0.f, 0.f};
            auto stageB = [&](int ck) {
                int buf = ck & 1;
                const char* us = g_Uimg + ((size_t)(c * 16 + ck) * 2) * 16384;
                #pragma unroll
                for (int i = 0; i < 4; ++i) {
                    int idx = i * 512 + tid;
                    cp16(sb + buf * 32768 + idx * 16, us + idx * 16);
                }
                // hx: v = gh * hm, hi/lo split, swizzled STS
                float gh = gh_s[ck >> 2][hb_b];
                const float* hsrc = &g_hm[hb_b][ck * 128 + hb_sg * 8];
                float4 v0 = *(const float4*)hsrc;
                float4 v1 = *(const float4*)(hsrc + 4);
                float vv[8] = {v0.x, v0.y, v0.z, v0.w, v1.x, v1.y, v1.z, v1.w};
                __nv_bfloat16 hb8[8], lb8[8];
                #pragma unroll
                for (int j = 0; j < 8; ++j) {
                    float v = gh * vv[j];
                    hb8[j] = __float2bfloat16(v);
                    lb8[j] = __float2bfloat16(v - __bfloat162float(hb8[j]));
                }
                unsigned byte = SWZ((unsigned)((hb_b >> 3) * 1024 + (hb_sg >> 3) * 4096 +
                                               (hb_b & 7) * 128 + (hb_sg & 7) * 16));
                char* hdst = smc + 65536 + buf * 16384;
                *(uint4*)(hdst + byte) = *(uint4*)hb8;
                *(uint4*)(hdst + 8192 + byte) = *(uint4*)lb8;
            };

            stageB(0);
            CP_COMMIT();
            for (int ck = 0; ck < 16; ++ck) {
                if (ck < 15) {
                    stageB(ck + 1);
                    CP_COMMIT();
                    CP_WAIT(1);
                } else {
                    CP_WAIT(0);
                }
                __syncthreads();

                uint32_t auh = sb + (ck & 1) * 32768, aul = auh + 16384;
                uint32_t buh = sb + 65536 + (ck & 1) * 16384, bul = buh + 8192;
                #pragma unroll
                for (int g = 0; g < 4; ++g) {
                    uint32_t baddr = (g >> 1) * 4096 + (cs * 8 + (lane & 7)) * 128 +
                                     (g & 1) * 64 + (lane >> 3) * 16;
                    uint32_t bh[4], bl_[4];
                    ldsm_x4(bh,  buh + SWZ(baddr));
                    ldsm_x4(bl_, bul + SWZ(baddr));
                    #pragma unroll
                    for (int sh = 0; sh < 2; ++sh) {
                        int s = g * 2 + sh;
                        uint32_t aaddr = (s >> 2) * 8192 + (rs * 16 + (lane & 15)) * 128 +
                                         (s & 3) * 32 + (lane >> 4) * 16;
                        uint32_t ah[4], al_[4];
                        ldsm_x4(ah,  auh + SWZ(aaddr));
                        ldsm_x4(al_, aul + SWZ(aaddr));
                        mma_bf16(d, ah,  bh[2 * sh],  bh[2 * sh + 1]);
                        mma_bf16(d, ah,  bl_[2 * sh], bl_[2 * sh + 1]);
                        mma_bf16(d, al_, bh[2 * sh],  bh[2 * sh + 1]);
                    }
                }
                __syncthreads();
            }
            int m = c * 64 + rs * 16 + (lane >> 2);
            int n = cs * 8 + (lane & 3) * 2;
            g_ugemm[n][m]         = d[0];
            g_ugemm[n + 1][m]     = d[1];
            g_ugemm[n][m + 8]     = d[2];
            g_ugemm[n + 1][m + 8] = d[3];
        }
        grid_sync();

        // ===== C: serial layer chain (W-GEMM on mma.sync + cell update) =====
        #pragma unroll
        for (int l = 0; l < 4; ++l) {
            if (l == 0 && c == 0 && tid < 128)
                g_gsum[par][tid >> 5][tid & 31] = 0.f;   // dead buffer, reused by C(t+1)

            const char* isrc = (l == 0) ? (g_xpimg + (size_t)t * 65536)
                                        : (g_hinimg + (size_t)(l - 1) * 65536);
            #pragma unroll
            for (int i = 0; i < 8; ++i) {
                int idx = i * 512 + tid;
                cp16(sb + idx * 16, isrc + idx * 16);
            }
            if (l == 0) {
                const char* wsrc = g_Wimg + ((size_t)c * 2) * 16384;
                #pragma unroll
                for (int i = 0; i < 4; ++i) {
                    int idx = i * 512 + tid;
                    cp16(sb + 65536 + idx * 16, wsrc + idx * 16);
                }
            }
            CP_COMMIT();
            if (l < 3) {
                const char* wsrc = g_Wimg + ((size_t)((l + 1) * 128 + c) * 2) * 16384;
                uint32_t wdst = sb + 65536 + ((l + 1) & 1) * 32768;
                #pragma unroll
                for (int i = 0; i < 4; ++i) {
                    int idx = i * 512 + tid;
                    cp16(wdst + idx * 16, wsrc + idx * 16);
                }
                CP_COMMIT();
                CP_WAIT(1);
            } else {
                CP_WAIT(0);
            }
            __syncthreads();

            float ug = g_ugemm[cb][l * G4 + crow];

            float dd[4] = {0.f, 0.f, 0.f, 0.f};
            uint32_t wh = sb + 65536 + (l & 1) * 32768, wl = wh + 16384;
            uint32_t ih = sb, il = sb + 32768;
            #pragma unroll
            for (int gg = 0; gg < 4; ++gg) {
                uint32_t baddr = (ks * 2 + (gg >> 1)) * 4096 + (ns * 8 + (lane & 7)) * 128 +
                                 (gg & 1) * 64 + (lane >> 3) * 16;
                uint32_t bh[4], bl_[4];
                ldsm_x4(bh,  ih + SWZ(baddr));
                ldsm_x4(bl_, il + SWZ(baddr));
                #pragma unroll
                for (int jh = 0; jh < 2; ++jh) {
                    int s = ks * 8 + gg * 2 + jh;
                    uint32_t aaddr = (s >> 2) * 2048 + (lane & 15) * 128 +
                                     (s & 3) * 32 + (lane >> 4) * 16;
                    uint32_t ah[4], al_[4];
                    ldsm_x4(ah,  wh + SWZ(aaddr));
                    ldsm_x4(al_, wl + SWZ(aaddr));
                    mma_bf16(dd, ah,  bh[2 * jh],  bh[2 * jh + 1]);
                    mma_bf16(dd, ah,  bl_[2 * jh], bl_[2 * jh + 1]);
                    mma_bf16(dd, al_, bh[2 * jh],  bh[2 * jh + 1]);
                }
            }
            {
                int m0 = lane >> 2, n0 = ns * 8 + (lane & 3) * 2;
                red[ks][m0][n0]         = dd[0];
                red[ks][m0][n0 + 1]     = dd[1];
                red[ks][m0 + 8][n0]     = dd[2];
                red[ks][m0 + 8][n0 + 1] = dd[3];
            }
            __syncthreads();

            float a = red[0][r16][cb] + red[1][r16][cb] +
                      red[2][r16][cb] + red[3][r16][cb] + ug;
            float act = (q == 2) ? tanh_f(a) : sigm(a);
            sm_g[r16][cb] = act;
            __syncthreads();
            if (q == 0) {
                float gf  = sm_g[4 + ms][cb];
                float gg_ = sm_g[8 + ms][cb];
                float go  = sm_g[12 + ms][cb];
                float cold = g_c[l][cb][mg];
                float cn = gf * cold + act * gg_;
                float hy = go * tanh_f(cn);
                g_c[l][cb][mg] = cn;
                g_h[l][cb][mg] = hy;

                // feed A-fold: hm for next step's U-GEMM + gate-sum partial
                float hm_n = hy * muv[l];
                g_hm[cb][l * 512 + mg] = hm_n;
                float s = hm_n * Gv[l];
                s += __shfl_xor_sync(0xFFu, s, 2);
                s += __shfl_xor_sync(0xFFu, s, 4);
                if (lane < 2) atomicAdd(&g_gsum[par ^ 1][l][cb], s);

                if (l < 3) {
                    float hv = hy * mwv[l];
                    __nv_bfloat16 hb = __float2bfloat16(hv);
                    __nv_bfloat16 lb = __float2bfloat16(hv - __bfloat162float(hb));
                    int seg = mg >> 3;
                    unsigned byte = SWZ((unsigned)((cb >> 3) * 1024 + (seg >> 3) * 4096 +
                                                   (cb & 7) * 128 + (seg & 7) * 16 + (mg & 7) * 2));
                    char* base = g_hinimg + (size_t)l * 65536;
                    *(__nv_bfloat16*)(base + byte) = hb;
                    *(__nv_bfloat16*)(base + 32768 + byte) = lb;
                }
            }
            grid_sync();
        }
    }

    const float* hp = &g_h[0][0][0];
    const float* cp = &g_c[0][0][0];
    for (int idx = c * NTHR + tid; idx < L * BATCH * H; idx += NCTA * NTHR) {
        out_h[idx] = hp[idx];
        out_c[idx] = cp[idx];
    }
}

// ---- launch ----
extern "C" void kernel_launch(void* const* d_in, const int* in_sizes, int n_in,
                              void* d_out, int out_size)
{
    const float* x      = (const float*)d_in[0];
    const float* lin_w  = (const float*)d_in[1];
    const float* lin_b  = (const float*)d_in[2];
    const float* W      = (const float*)d_in[3];
    const float* U      = (const float*)d_in[4];
    const float* G      = (const float*)d_in[5];
    const float* mask_u = (const float*)d_in[6];
    const float* mask_w = (const float*)d_in[7];
    const float* h0     = (const float*)d_in[8];
    const float* c0     = (const float*)d_in[9];
    float* out = (float*)d_out;
    (void)in_sizes; (void)n_in; (void)out_size;

    prep_U_img<<<128 * 16, 256>>>(U);
    prep_W_img<<<4 * 128, 256>>>(W);
    xp_kernel<<<(TT * BATCH) / 16, 256>>>(x, lin_w, lin_b, mask_w);
    reset_gsum<<<1, 256>>>();
    init_hc<<<64, 256>>>(h0, c0, mask_u, G);

    cudaFuncSetAttribute(rnn_kernel, cudaFuncAttributeMaxDynamicSharedMemorySize, SMEM_DYN);
    rnn_kernel<<<NCTA, NTHR, SMEM_DYN>>>(G, mask_u, mask_w, out);
}

// round 9
// speedup vs baseline: 1.2584x; 1.1495x over previous
#include <cuda_runtime.h>
#include <cuda_bf16.h>
#include <math.h>
#include <stdint.h>

#define L     4
#define H     512
#define BATCH 32
#define TT    1024
#define G4    2048
#define LH    2048
#define JTOT  8192
#define NCTA  128
#define NTHR  512

#define SWZ(o) ((unsigned)(o) ^ (((unsigned)(o) >> 3) & 0x70u))

// ---- PTX helpers (base-target features only) ----
__device__ __forceinline__ uint32_t smem_u32(const void* p) {
    uint32_t a;
    asm("{ .reg .u64 t; cvta.to.shared.u64 t, %1; cvt.u32.u64 %0, t; }" : "=r"(a) : "l"(p));
    return a;
}
__device__ __forceinline__ void cp16(uint32_t dst, const void* src) {
    asm volatile("cp.async.cg.shared.global [%0], [%1], 16;" :: "r"(dst), "l"(src) : "memory");
}
#define CP_COMMIT() asm volatile("cp.async.commit_group;" ::: "memory")
#define CP_WAIT(n)  asm volatile("cp.async.wait_group %0;" :: "n"(n) : "memory")

__device__ __forceinline__ void ldsm_x4(uint32_t* r, uint32_t addr) {
    asm volatile("ldmatrix.sync.aligned.m8n8.x4.shared.b16 {%0,%1,%2,%3}, [%4];"
        : "=r"(r[0]), "=r"(r[1]), "=r"(r[2]), "=r"(r[3]) : "r"(addr));
}
__device__ __forceinline__ void mma_bf16(float* d, const uint32_t* a, uint32_t b0, uint32_t b1) {
    asm volatile("mma.sync.aligned.m16n8k16.row.col.f32.bf16.bf16.f32 "
        "{%0,%1,%2,%3}, {%4,%5,%6,%7}, {%8,%9}, {%0,%1,%2,%3};"
        : "+f"(d[0]), "+f"(d[1]), "+f"(d[2]), "+f"(d[3])
        : "r"(a[0]), "r"(a[1]), "r"(a[2]), "r"(a[3]), "r"(b0), "r"(b1));
}
__device__ __forceinline__ float sigm(float x) { return 1.f / (1.f + __expf(-x)); }
__device__ __forceinline__ float tanh_f(float x) { return 1.f - 2.f / (1.f + __expf(2.f * x)); }

// ---- static device scratch ----
__device__ __align__(16) char g_Uimg[(size_t)128 * 16 * 2 * 16384];  // [c][chunk][hl] 16KB
__device__ __align__(16) char g_Wimg[(size_t)4 * 128 * 2 * 16384];   // [l][c][hl] 16KB
__device__ __align__(16) char g_xpimg[(size_t)TT * 2 * 32768];       // [t][hl] 32KB
__device__ __align__(16) char g_hinimg[(size_t)3 * 2 * 32768];       // [l][hl]
__device__ __align__(16) char g_hximg[(size_t)16 * 2 * 8192];        // [chunk][hl]
__device__ float g_h[L][BATCH][H];
__device__ float g_c[L][BATCH][H];
__device__ float g_ugemm[BATCH][JTOT];
__device__ unsigned g_cnt = 0;
__device__ volatile unsigned g_gen = 0;

// ---- software grid barrier (R6-proven) ----
__device__ __forceinline__ void grid_sync()
{
    __syncthreads();
    if (threadIdx.x == 0) {
        unsigned g = g_gen;
        __threadfence();
        if (atomicAdd(&g_cnt, 1u) == NCTA - 1u) {
            g_cnt = 0;
            __threadfence();
            g_gen = g + 1u;
        } else {
            while (g_gen == g) { }
        }
        __threadfence();
    }
    __syncthreads();
}

// ---- prep kernels ----
__global__ void prep_U_img(const float* __restrict__ U)
{
    int blk = blockIdx.x;                 // c*16 + chunk
    int c = blk >> 4, chunk = blk & 15;
    char* dsth = g_Uimg + ((size_t)blk * 2) * 16384;
    char* dstl = dsth + 16384;
    for (int i = threadIdx.x; i < 1024; i += 256) {
        int r = i >> 4, s8 = i & 15;
        const float* src = U + ((size_t)(c * 64 + r)) * LH + chunk * 128 + s8 * 8;
        __nv_bfloat16 hb[8], lb[8];
        #pragma unroll
        for (int j = 0; j < 8; ++j) {
            float v = src[j];
            hb[j] = __float2bfloat16(v);
            lb[j] = __float2bfloat16(v - __bfloat162float(hb[j]));
        }
        unsigned byte = SWZ((unsigned)((r >> 3) * 1024 + (s8 >> 3) * 8192 +
                                       (r & 7) * 128 + (s8 & 7) * 16));
        *(uint4*)(dsth + byte) = *(uint4*)hb;
        *(uint4*)(dstl + byte) = *(uint4*)lb;
    }
}

__global__ void prep_W_img(const float* __restrict__ W)
{
    int blk = blockIdx.x;                 // l*128 + c
    int l = blk >> 7, c = blk & 127;
    char* dsth = g_Wimg + ((size_t)blk * 2) * 16384;
    char* dstl = dsth + 16384;
    for (int i = threadIdx.x; i < 1024; i += 256) {
        int r = i >> 6, s8 = i & 63;
        int q = r >> 2, ms = r & 3;
        int wrow = q * 512 + c * 4 + ms;
        const float* src = W + ((size_t)(l * G4 + wrow)) * H + s8 * 8;
        __nv_bfloat16 hb[8], lb[8];
        #pragma unroll
        for (int j = 0; j < 8; ++j) {
            float v = src[j];
            hb[j] = __float2bfloat16(v);
            lb[j] = __float2bfloat16(v - __bfloat162float(hb[j]));
        }
        unsigned byte = SWZ((unsigned)((r >> 3) * 1024 + (s8 >> 3) * 2048 +
                                       (r & 7) * 128 + (s8 & 7) * 16));
        *(uint4*)(dsth + byte) = *(uint4*)hb;
        *(uint4*)(dstl + byte) = *(uint4*)lb;
    }
}

__global__ void xp_kernel(const float* __restrict__ x,
                          const float* __restrict__ lin_w,
                          const float* __restrict__ lin_b,
                          const float* __restrict__ mask_w)
{
    __shared__ float xs[16][128];
    int tb0 = blockIdx.x * 16;
    int tid = threadIdx.x;
    #pragma unroll
    for (int r = 0; r < 8; ++r) {
        int e = r * 256 + tid;
        xs[e >> 7][e & 127] = x[(size_t)(tb0 + (e >> 7)) * 128 + (e & 127)];
    }
    __syncthreads();
    int h0 = tid, h1 = tid + 256;
    const float* w0 = lin_w + (size_t)h0 * 128;
    const float* w1 = lin_w + (size_t)h1 * 128;
    float acc0[16], acc1[16];
    #pragma unroll
    for (int p = 0; p < 16; ++p) { acc0[p] = 0.f; acc1[p] = 0.f; }
    for (int i = 0; i < 128; i += 4) {
        float4 a = *(const float4*)(w0 + i);
        float4 b = *(const float4*)(w1 + i);
        #pragma unroll
        for (int p = 0; p < 16; ++p) {
            float4 xv = *(const float4*)&xs[p][i];
            acc0[p] += a.x * xv.x + a.y * xv.y + a.z * xv.z + a.w * xv.w;
            acc1[p] += b.x * xv.x + b.y * xv.y + b.z * xv.z + b.w * xv.w;
        }
    }
    float b0 = lin_b[h0], b1 = lin_b[h1];
    #pragma unroll
    for (int p = 0; p < 16; ++p) {
        int tb = tb0 + p;
        int tt = tb >> 5, bb = tb & 31;
        char* base = g_xpimg + (size_t)tt * 65536;
        #pragma unroll
        for (int cc = 0; cc < 2; ++cc) {
            int hh = cc ? h1 : h0;
            float v = ((cc ? acc1[p] : acc0[p]) + (cc ? b1 : b0)) *
                      mask_w[(size_t)bb * H + hh];
            __nv_bfloat16 hb = __float2bfloat16(v);
            __nv_bfloat16 lb = __float2bfloat16(v - __bfloat162float(hb));
            int seg = hh >> 3;
            unsigned byte = SWZ((unsigned)((bb >> 3) * 1024 + (seg >> 3) * 4096 +
                                           (bb & 7) * 128 + (seg & 7) * 16 + (hh & 7) * 2));
            *(__nv_bfloat16*)(base + byte) = hb;
            *(__nv_bfloat16*)(base + 32768 + byte) = lb;
        }
    }
}

__global__ void init_hc(const float* __restrict__ h0, const float* __restrict__ c0)
{
    float* hp = &g_h[0][0][0];
    float* cp = &g_c[0][0][0];
    for (int i = blockIdx.x * blockDim.x + threadIdx.x; i < L * BATCH * H;
         i += gridDim.x * blockDim.x)
        { hp[i] = h0[i]; cp[i] = c0[i]; }
}

// ---- persistent kernel ----
// dyn SMEM union: B: Ubuf 2x32K @0, hxbuf 2x16K @65536 | C: inp 64K @0, W 2x32K @65536
#define SMEM_DYN (131072 + 1024)

__global__ void __launch_bounds__(NTHR, 1)
rnn_kernel(const float* __restrict__ G,
           const float* __restrict__ mask_u,
           const float* __restrict__ mask_w,
           float* __restrict__ out)
{
    extern __shared__ char smc_raw[];
    __shared__ float redA[16];
    __shared__ float ghA;
    __shared__ float sm_g[16][33];
    __shared__ float red[4][16][33];

    const int c    = blockIdx.x;
    const int tid  = threadIdx.x;
    const int wid  = tid >> 5;
    const int lane = tid & 31;

    uint32_t sbr = smem_u32(smc_raw);
    uint32_t sb  = (sbr + 1023u) & ~1023u;

    // A: CTA = (layer, batch)
    const int al  = c & 3;
    const int abt = c >> 2;
    // B: warp = 4 J strips x 4 batch strips
    const int rs = wid >> 2;
    const int cs = wid & 3;
    // C: warp = (K split, batch strip); thread = (row r16, batch cb)
    const int ks = wid >> 2;
    const int ns = wid & 3;
    const int cb   = wid * 2 + (lane & 1);
    const int r16  = lane >> 1;
    const int q    = r16 >> 2;
    const int ms   = r16 & 3;
    const int mg   = c * 4 + ms;
    const int crow = q * 512 + mg;

    // hoisted per-thread constants
    const float Gv   = G[al * H + tid];
    const float muv  = mask_u[((size_t)(al * BATCH + abt)) * H + tid];
    float mwv[3];
    #pragma unroll
    for (int l = 0; l < 3; ++l)
        mwv[l] = mask_w[((size_t)((l + 1) * BATCH + cb)) * H + mg];

    float* out_h = out;
    float* out_c = out + L * BATCH * H;
    float* out_g = out + 2 * L * BATCH * H;

    for (int t = 0; t < TT; ++t) {
        // ===== A: hx build for (al, abt), write swizzled bf16 image =====
        {
            float hm = g_h[al][abt][tid] * muv;
            float s  = hm * Gv;
            #pragma unroll
            for (int o = 16; o; o >>= 1) s += __shfl_xor_sync(~0u, s, o);
            if (lane == 0) redA[wid] = s;
            __syncthreads();
            if (tid == 0) {
                float ss = 0.f;
                #pragma unroll
                for (int r = 0; r < 16; ++r) ss += redA[r];
                float gh = sigm(ss);
                ghA = gh;
                out_g[(size_t)(al * BATCH + abt) * TT + t] = gh;
            }
            __syncthreads();
            float v = ghA * hm;
            __nv_bfloat16 hb = __float2bfloat16(v);
            __nv_bfloat16 lb = __float2bfloat16(v - __bfloat162float(hb));
            int kg = al * 512 + tid;
            int chunk = kg >> 7, kl = kg & 127, seg = kl >> 3;
            unsigned byte = SWZ((unsigned)((abt >> 3) * 1024 + (seg >> 3) * 4096 +
                                           (abt & 7) * 128 + (seg & 7) * 16 + (kl & 7) * 2));
            char* base = g_hximg + (size_t)chunk * 16384;
            *(__nv_bfloat16*)(base + byte) = hb;
            *(__nv_bfloat16*)(base + 8192 + byte) = lb;
        }
        grid_sync();

        // ===== B: U-GEMM (bf16x3), 3 independent accumulator chains =====
        {
            float dhh[4] = {0.f, 0.f, 0.f, 0.f};
            float dhl[4] = {0.f, 0.f, 0.f, 0.f};
            float dlh[4] = {0.f, 0.f, 0.f, 0.f};

            auto stageB = [&](int ck) {
                int buf = ck & 1;
                const char* us = g_Uimg + ((size_t)(c * 16 + ck) * 2) * 16384;
                #pragma unroll
                for (int i = 0; i < 4; ++i) {
                    int idx = i * 512 + tid;
                    cp16(sb + buf * 32768 + idx * 16, us + idx * 16);
                }
                const char* hs = g_hximg + (size_t)ck * 2 * 8192;
                #pragma unroll
                for (int i = 0; i < 2; ++i) {
                    int idx = i * 512 + tid;
                    cp16(sb + 65536 + buf * 16384 + idx * 16, hs + idx * 16);
                }
            };

            stageB(0);
            CP_COMMIT();
            for (int ck = 0; ck < 16; ++ck) {
                if (ck < 15) {
                    stageB(ck + 1);
                    CP_COMMIT();
                    CP_WAIT(1);
                } else {
                    CP_WAIT(0);
                }
                __syncthreads();

                uint32_t auh = sb + (ck & 1) * 32768, aul = auh + 16384;
                uint32_t buh = sb + 65536 + (ck & 1) * 16384, bul = buh + 8192;
                #pragma unroll
                for (int g = 0; g < 4; ++g) {
                    uint32_t baddr = (g >> 1) * 4096 + (cs * 8 + (lane & 7)) * 128 +
                                     (g & 1) * 64 + (lane >> 3) * 16;
                    uint32_t bh[4], bl_[4];
                    ldsm_x4(bh,  buh + SWZ(baddr));
                    ldsm_x4(bl_, bul + SWZ(baddr));
                    #pragma unroll
                    for (int sh = 0; sh < 2; ++sh) {
                        int s = g * 2 + sh;
                        uint32_t aaddr = (s >> 2) * 8192 + (rs * 16 + (lane & 15)) * 128 +
                                         (s & 3) * 32 + (lane >> 4) * 16;
                        uint32_t ah[4], al_[4];
                        ldsm_x4(ah,  auh + SWZ(aaddr));
                        ldsm_x4(al_, aul + SWZ(aaddr));
                        mma_bf16(dhh, ah,  bh[2 * sh],  bh[2 * sh + 1]);
                        mma_bf16(dhl, ah,  bl_[2 * sh], bl_[2 * sh + 1]);
                        mma_bf16(dlh, al_, bh[2 * sh],  bh[2 * sh + 1]);
                    }
                }
                __syncthreads();
            }
            int m = c * 64 + rs * 16 + (lane >> 2);
            int n = cs * 8 + (lane & 3) * 2;
            g_ugemm[n][m]         = dhh[0] + dhl[0] + dlh[0];
            g_ugemm[n + 1][m]     = dhh[1] + dhl[1] + dlh[1];
            g_ugemm[n][m + 8]     = dhh[2] + dhl[2] + dlh[2];
            g_ugemm[n + 1][m + 8] = dhh[3] + dhl[3] + dlh[3];
        }
        grid_sync();

        // ===== C: serial layer chain, W-GEMM on mma.sync (3 chains) =====
        #pragma unroll
        for (int l = 0; l < 4; ++l) {
            const char* isrc = (l == 0) ? (g_xpimg + (size_t)t * 65536)
                                        : (g_hinimg + (size_t)(l - 1) * 65536);
            #pragma unroll
            for (int i = 0; i < 8; ++i) {
                int idx = i * 512 + tid;
                cp16(sb + idx * 16, isrc + idx * 16);
            }
            if (l == 0) {
                const char* wsrc = g_Wimg + ((size_t)c * 2) * 16384;
                #pragma unroll
                for (int i = 0; i < 4; ++i) {
                    int idx = i * 512 + tid;
                    cp16(sb + 65536 + idx * 16, wsrc + idx * 16);
                }
            }
            CP_COMMIT();
            if (l < 3) {
                const char* wsrc = g_Wimg + ((size_t)((l + 1) * 128 + c) * 2) * 16384;
                uint32_t wdst = sb + 65536 + ((l + 1) & 1) * 32768;
                #pragma unroll
                for (int i = 0; i < 4; ++i) {
                    int idx = i * 512 + tid;
                    cp16(wdst + idx * 16, wsrc + idx * 16);
                }
                CP_COMMIT();
                CP_WAIT(1);
            } else {
                CP_WAIT(0);
            }
            __syncthreads();

            float ug = g_ugemm[cb][l * G4 + crow];

            float dhh[4] = {0.f, 0.f, 0.f, 0.f};
            float dhl[4] = {0.f, 0.f, 0.f, 0.f};
            float dlh[4] = {0.f, 0.f, 0.f, 0.f};
            uint32_t wh = sb + 65536 + (l & 1) * 32768, wl = wh + 16384;
            uint32_t ih = sb, il = sb + 32768;
            #pragma unroll
            for (int gg = 0; gg < 4; ++gg) {
                uint32_t baddr = (ks * 2 + (gg >> 1)) * 4096 + (ns * 8 + (lane & 7)) * 128 +
                                 (gg & 1) * 64 + (lane >> 3) * 16;
                uint32_t bh[4], bl_[4];
                ldsm_x4(bh,  ih + SWZ(baddr));
                ldsm_x4(bl_, il + SWZ(baddr));
                #pragma unroll
                for (int jh = 0; jh < 2; ++jh) {
                    int s = ks * 8 + gg * 2 + jh;
                    uint32_t aaddr = (s >> 2) * 2048 + (lane & 15) * 128 +
                                     (s & 3) * 32 + (lane >> 4) * 16;
                    uint32_t ah[4], al_[4];
                    ldsm_x4(ah,  wh + SWZ(aaddr));
                    ldsm_x4(al_, wl + SWZ(aaddr));
                    mma_bf16(dhh, ah,  bh[2 * jh],  bh[2 * jh + 1]);
                    mma_bf16(dhl, ah,  bl_[2 * jh], bl_[2 * jh + 1]);
                    mma_bf16(dlh, al_, bh[2 * jh],  bh[2 * jh + 1]);
                }
            }
            {
                int m0 = lane >> 2, n0 = ns * 8 + (lane & 3) * 2;
                red[ks][m0][n0]         = dhh[0] + dhl[0] + dlh[0];
                red[ks][m0][n0 + 1]     = dhh[1] + dhl[1] + dlh[1];
                red[ks][m0 + 8][n0]     = dhh[2] + dhl[2] + dlh[2];
                red[ks][m0 + 8][n0 + 1] = dhh[3] + dhl[3] + dlh[3];
            }
            __syncthreads();

            float a = red[0][r16][cb] + red[1][r16][cb] +
                      red[2][r16][cb] + red[3][r16][cb] + ug;
            float act = (q == 2) ? tanh_f(a) : sigm(a);
            sm_g[r16][cb] = act;
            __syncthreads();
            if (q == 0) {
                float gf  = sm_g[4 + ms][cb];
                float gg_ = sm_g[8 + ms][cb];
                float go  = sm_g[12 + ms][cb];
                float cold = g_c[l][cb][mg];
                float cn = gf * cold + act * gg_;
                float hy = go * tanh_f(cn);
                g_c[l][cb][mg] = cn;
                g_h[l][cb][mg] = hy;
                if (l < 3) {
                    float hv = hy * mwv[l];
                    __nv_bfloat16 hb = __float2bfloat16(hv);
                    __nv_bfloat16 lb = __float2bfloat16(hv - __bfloat162float(hb));
                    int seg = mg >> 3;
                    unsigned byte = SWZ((unsigned)((cb >> 3) * 1024 + (seg >> 3) * 4096 +
                                                   (cb & 7) * 128 + (seg & 7) * 16 + (mg & 7) * 2));
                    char* base = g_hinimg + (size_t)l * 65536;
                    *(__nv_bfloat16*)(base + byte) = hb;
                    *(__nv_bfloat16*)(base + 32768 + byte) = lb;
                }
            }
            grid_sync();
        }
    }

    const float* hp = &g_h[0][0][0];
    const float* cp = &g_c[0][0][0];
    for (int idx = c * NTHR + tid; idx < L * BATCH * H; idx += NCTA * NTHR) {
        out_h[idx] = hp[idx];
        out_c[idx] = cp[idx];
    }
}

// ---- launch ----
extern "C" void kernel_launch(void* const* d_in, const int* in_sizes, int n_in,
                              void* d_out, int out_size)
{
    const float* x      = (const float*)d_in[0];
    const float* lin_w  = (const float*)d_in[1];
    const float* lin_b  = (const float*)d_in[2];
    const float* W      = (const float*)d_in[3];
    const float* U      = (const float*)d_in[4];
    const float* G      = (const float*)d_in[5];
    const float* mask_u = (const float*)d_in[6];
    const float* mask_w = (const float*)d_in[7];
    const float* h0     = (const float*)d_in[8];
    const float* c0     = (const float*)d_in[9];
    float* out = (float*)d_out;
    (void)in_sizes; (void)n_in; (void)out_size;

    prep_U_img<<<128 * 16, 256>>>(U);
    prep_W_img<<<4 * 128, 256>>>(W);
    xp_kernel<<<(TT * BATCH) / 16, 256>>>(x, lin_w, lin_b, mask_w);
    init_hc<<<64, 256>>>(h0, c0);

    cudaFuncSetAttribute(rnn_kernel, cudaFuncAttributeMaxDynamicSharedMemorySize, SMEM_DYN);
    rnn_kernel<<<NCTA, NTHR, SMEM_DYN>>>(G, mask_u, mask_w, out);
}

// round 10
// speedup vs baseline: 1.2868x; 1.0226x over previous
#include <cuda_runtime.h>
#include <cuda_bf16.h>
#include <math.h>
#include <stdint.h>

#define L     4
#define H     512
#define BATCH 32
#define TT    1024
#define G4    2048
#define LH    2048
#define JTOT  8192
#define NCTA  128
#define NTHR  512

#define SWZ(o) ((unsigned)(o) ^ (((unsigned)(o) >> 3) & 0x70u))

// ---- PTX helpers (base-target features only) ----
__device__ __forceinline__ uint32_t smem_u32(const void* p) {
    uint32_t a;
    asm("{ .reg .u64 t; cvta.to.shared.u64 t, %1; cvt.u32.u64 %0, t; }" : "=r"(a) : "l"(p));
    return a;
}
__device__ __forceinline__ void cp16(uint32_t dst, const void* src) {
    asm volatile("cp.async.cg.shared.global [%0], [%1], 16;" :: "r"(dst), "l"(src) : "memory");
}
#define CP_COMMIT() asm volatile("cp.async.commit_group;" ::: "memory")
#define CP_WAIT(n)  asm volatile("cp.async.wait_group %0;" :: "n"(n) : "memory")

__device__ __forceinline__ void ldsm_x4(uint32_t* r, uint32_t addr) {
    asm volatile("ldmatrix.sync.aligned.m8n8.x4.shared.b16 {%0,%1,%2,%3}, [%4];"
        : "=r"(r[0]), "=r"(r[1]), "=r"(r[2]), "=r"(r[3]) : "r"(addr));
}
__device__ __forceinline__ void mma_bf16(float* d, const uint32_t* a, uint32_t b0, uint32_t b1) {
    asm volatile("mma.sync.aligned.m16n8k16.row.col.f32.bf16.bf16.f32 "
        "{%0,%1,%2,%3}, {%4,%5,%6,%7}, {%8,%9}, {%0,%1,%2,%3};"
        : "+f"(d[0]), "+f"(d[1]), "+f"(d[2]), "+f"(d[3])
        : "r"(a[0]), "r"(a[1]), "r"(a[2]), "r"(a[3]), "r"(b0), "r"(b1));
}
__device__ __forceinline__ void wait_cnt(const unsigned* p, unsigned target) {
    unsigned v;
    do {
        asm volatile("ld.acquire.gpu.global.u32 %0, [%1];" : "=r"(v) : "l"(p) : "memory");
    } while (v < target);
}
__device__ __forceinline__ float sigm(float x) { return 1.f / (1.f + __expf(-x)); }
__device__ __forceinline__ float tanh_f(float x) { return 1.f - 2.f / (1.f + __expf(2.f * x)); }

// ---- static device scratch ----
__device__ __align__(16) char g_Uimg[(size_t)128 * 16 * 2 * 16384];  // [c][chunk][hl] 16KB
__device__ __align__(16) char g_Wimg[(size_t)4 * 128 * 2 * 16384];   // [l][c][hl] 16KB
__device__ __align__(16) char g_xpimg[(size_t)TT * 2 * 32768];       // [t][hl] 32KB
__device__ __align__(16) char g_hinimg[(size_t)3 * 2 * 32768];       // [l][hl]
__device__ __align__(16) char g_hximg[(size_t)16 * 2 * 8192];        // [chunk][hl]
__device__ float g_h[L][BATCH][H];
__device__ float g_c[L][BATCH][H];
__device__ float g_ugemm[BATCH][JTOT];
__device__ unsigned g_cntA3;
__device__ unsigned g_cnt = 0;
__device__ volatile unsigned g_gen = 0;

// ---- software grid barrier (R6-proven) ----
__device__ __forceinline__ void grid_sync()
{
    __syncthreads();
    if (threadIdx.x == 0) {
        unsigned g = g_gen;
        __threadfence();
        if (atomicAdd(&g_cnt, 1u) == NCTA - 1u) {
            g_cnt = 0;
            __threadfence();
            g_gen = g + 1u;
        } else {
            while (g_gen == g) { }
        }
        __threadfence();
    }
    __syncthreads();
}

// ---- prep kernels (merged: U blocks 0..2047, W blocks 2048..2559) ----
__global__ void prep_all(const float* __restrict__ U, const float* __restrict__ W)
{
    if (blockIdx.x < 2048) {
        int blk = blockIdx.x;                 // c*16 + chunk
        int c = blk >> 4, chunk = blk & 15;
        char* dsth = g_Uimg + ((size_t)blk * 2) * 16384;
        char* dstl = dsth + 16384;
        for (int i = threadIdx.x; i < 1024; i += 256) {
            int r = i >> 4, s8 = i & 15;
            const float* src = U + ((size_t)(c * 64 + r)) * LH + chunk * 128 + s8 * 8;
            __nv_bfloat16 hb[8], lb[8];
            #pragma unroll
            for (int j = 0; j < 8; ++j) {
                float v = src[j];
                hb[j] = __float2bfloat16(v);
                lb[j] = __float2bfloat16(v - __bfloat162float(hb[j]));
            }
            unsigned byte = SWZ((unsigned)((r >> 3) * 1024 + (s8 >> 3) * 8192 +
                                           (r & 7) * 128 + (s8 & 7) * 16));
            *(uint4*)(dsth + byte) = *(uint4*)hb;
            *(uint4*)(dstl + byte) = *(uint4*)lb;
        }
    } else {
        int blk = blockIdx.x - 2048;          // l*128 + c
        int l = blk >> 7, c = blk & 127;
        char* dsth = g_Wimg + ((size_t)blk * 2) * 16384;
        char* dstl = dsth + 16384;
        for (int i = threadIdx.x; i < 1024; i += 256) {
            int r = i >> 6, s8 = i & 63;
            int q = r >> 2, ms = r & 3;
            int wrow = q * 512 + c * 4 + ms;
            const float* src = W + ((size_t)(l * G4 + wrow)) * H + s8 * 8;
            __nv_bfloat16 hb[8], lb[8];
            #pragma unroll
            for (int j = 0; j < 8; ++j) {
                float v = src[j];
                hb[j] = __float2bfloat16(v);
                lb[j] = __float2bfloat16(v - __bfloat162float(hb[j]));
            }
            unsigned byte = SWZ((unsigned)((r >> 3) * 1024 + (s8 >> 3) * 2048 +
                                           (r & 7) * 128 + (s8 & 7) * 16));
            *(uint4*)(dsth + byte) = *(uint4*)hb;
            *(uint4*)(dstl + byte) = *(uint4*)lb;
        }
    }
}

__global__ void xp_kernel(const float* __restrict__ x,
                          const float* __restrict__ lin_w,
                          const float* __restrict__ lin_b,
                          const float* __restrict__ mask_w)
{
    __shared__ float xs[16][128];
    int tb0 = blockIdx.x * 16;
    int tid = threadIdx.x;
    #pragma unroll
    for (int r = 0; r < 8; ++r) {
        int e = r * 256 + tid;
        xs[e >> 7][e & 127] = x[(size_t)(tb0 + (e >> 7)) * 128 + (e & 127)];
    }
    __syncthreads();
    int h0 = tid, h1 = tid + 256;
    const float* w0 = lin_w + (size_t)h0 * 128;
    const float* w1 = lin_w + (size_t)h1 * 128;
    float acc0[16], acc1[16];
    #pragma unroll
    for (int p = 0; p < 16; ++p) { acc0[p] = 0.f; acc1[p] = 0.f; }
    for (int i = 0; i < 128; i += 4) {
        float4 a = *(const float4*)(w0 + i);
        float4 b = *(const float4*)(w1 + i);
        #pragma unroll
        for (int p = 0; p < 16; ++p) {
            float4 xv = *(const float4*)&xs[p][i];
            acc0[p] += a.x * xv.x + a.y * xv.y + a.z * xv.z + a.w * xv.w;
            acc1[p] += b.x * xv.x + b.y * xv.y + b.z * xv.z + b.w * xv.w;
        }
    }
    float b0 = lin_b[h0], b1 = lin_b[h1];
    #pragma unroll
    for (int p = 0; p < 16; ++p) {
        int tb = tb0 + p;
        int tt = tb >> 5, bb = tb & 31;
        char* base = g_xpimg + (size_t)tt * 65536;
        #pragma unroll
        for (int cc = 0; cc < 2; ++cc) {
            int hh = cc ? h1 : h0;
            float v = ((cc ? acc1[p] : acc0[p]) + (cc ? b1 : b0)) *
                      mask_w[(size_t)bb * H + hh];
            __nv_bfloat16 hb = __float2bfloat16(v);
            __nv_bfloat16 lb = __float2bfloat16(v - __bfloat162float(hb));
            int seg = hh >> 3;
            unsigned byte = SWZ((unsigned)((bb >> 3) * 1024 + (seg >> 3) * 4096 +
                                           (bb & 7) * 128 + (seg & 7) * 16 + (hh & 7) * 2));
            *(__nv_bfloat16*)(base + byte) = hb;
            *(__nv_bfloat16*)(base + 32768 + byte) = lb;
        }
    }
}

__global__ void init_hc(const float* __restrict__ h0, const float* __restrict__ c0)
{
    if (blockIdx.x == 0 && threadIdx.x == 0) g_cntA3 = 0;
    float* hp = &g_h[0][0][0];
    float* cp = &g_c[0][0][0];
    for (int i = blockIdx.x * blockDim.x + threadIdx.x; i < L * BATCH * H;
         i += gridDim.x * blockDim.x)
        { hp[i] = h0[i]; cp[i] = c0[i]; }
}

// ---- persistent kernel ----
// dyn SMEM: B: Ubuf 4x32K @0..128K, hxbuf 4x16K @131072..196608
//           C (union, time-separated): inp 64K @0, Wbuf 2x32K @65536
#define SMEM_DYN (196608 + 1024)

__global__ void __launch_bounds__(NTHR, 1)
rnn_kernel(const float* __restrict__ G,
           const float* __restrict__ mask_u,
           const float* __restrict__ mask_w,
           float* __restrict__ out)
{
    extern __shared__ char smc_raw[];
    __shared__ float redA[16];
    __shared__ float ghA;
    __shared__ float sm_g[16][33];
    __shared__ float red[4][16][33];

    const int c    = blockIdx.x;
    const int tid  = threadIdx.x;
    const int wid  = tid >> 5;
    const int lane = tid & 31;

    uint32_t sbr = smem_u32(smc_raw);
    uint32_t sb  = (sbr + 1023u) & ~1023u;

    // A: CTA = (layer, batch)
    const int al  = c & 3;
    const int abt = c >> 2;
    // B: warp = 4 J strips x 4 batch strips
    const int rs = wid >> 2;
    const int cs = wid & 3;
    // C: warp = (K split, batch strip); thread = (row r16, batch cb)
    const int ks = wid >> 2;
    const int ns = wid & 3;
    const int cb   = wid * 2 + (lane & 1);
    const int r16  = lane >> 1;
    const int q    = r16 >> 2;
    const int ms   = r16 & 3;
    const int mg   = c * 4 + ms;
    const int crow = q * 512 + mg;

    // hoisted per-thread constants
    const float Gv   = G[al * H + tid];
    const float muv  = mask_u[((size_t)(al * BATCH + abt)) * H + tid];
    float mwv[3];
    #pragma unroll
    for (int l = 0; l < 3; ++l)
        mwv[l] = mask_w[((size_t)((l + 1) * BATCH + cb)) * H + mg];

    float* out_h = out;
    float* out_c = out + L * BATCH * H;
    float* out_g = out + 2 * L * BATCH * H;

    // A work for this CTA's (al, abt): gate + gated-masked hidden -> hx image.
    // t_out is the timestep index whose U-GEMM will consume this hx.
    auto do_A = [&](int t_out) {
        float hm = g_h[al][abt][tid] * muv;
        float s  = hm * Gv;
        #pragma unroll
        for (int o = 16; o; o >>= 1) s += __shfl_xor_sync(~0u, s, o);
        if (lane == 0) redA[wid] = s;
        __syncthreads();
        if (tid == 0) {
            float ss = 0.f;
            #pragma unroll
            for (int r = 0; r < 16; ++r) ss += redA[r];
            float gh = sigm(ss);
            ghA = gh;
            out_g[(size_t)(al * BATCH + abt) * TT + t_out] = gh;
        }
        __syncthreads();
        float v = ghA * hm;
        __nv_bfloat16 hb = __float2bfloat16(v);
        __nv_bfloat16 lb = __float2bfloat16(v - __bfloat162float(hb));
        int kg = al * 512 + tid;
        int chunk = kg >> 7, kl = kg & 127, seg = kl >> 3;
        unsigned byte = SWZ((unsigned)((abt >> 3) * 1024 + (seg >> 3) * 4096 +
                                       (abt & 7) * 128 + (seg & 7) * 16 + (kl & 7) * 2));
        char* base = g_hximg + (size_t)chunk * 16384;
        *(__nv_bfloat16*)(base + byte) = hb;
        *(__nv_bfloat16*)(base + 8192 + byte) = lb;
        if (al == 3) {
            __syncthreads();
            if (tid == 0) {
                __threadfence();
                atomicAdd(&g_cntA3, 1u);
            }
        }
    };

    // peel: A for t=0 (all layers), then one grid sync before B(0)
    do_A(0);
    grid_sync();

    for (int t = 0; t < TT; ++t) {
        // layer-3 A for step t (runs after C(t-1)'s final sync == top of this iter)
        if (t >= 1 && al == 3) do_A(t);

        // ===== B: U-GEMM (bf16x3), 4-buffer pipeline, 1 sync per chunk =====
        {
            float dhh[4] = {0.f, 0.f, 0.f, 0.f};
            float dhl[4] = {0.f, 0.f, 0.f, 0.f};
            float dlh[4] = {0.f, 0.f, 0.f, 0.f};

            auto stageB = [&](int ck) {
                if (ck == 12) wait_cnt(&g_cntA3, 32u * (unsigned)(t + 1));
                int buf = ck & 3;
                const char* us = g_Uimg + ((size_t)(c * 16 + ck) * 2) * 16384;
                #pragma unroll
                for (int i = 0; i < 4; ++i) {
                    int idx = i * 512 + tid;
                    cp16(sb + buf * 32768 + idx * 16, us + idx * 16);
                }
                const char* hs = g_hximg + (size_t)ck * 2 * 8192;
                #pragma unroll
                for (int i = 0; i < 2; ++i) {
                    int idx = i * 512 + tid;
                    cp16(sb + 131072 + buf * 16384 + idx * 16, hs + idx * 16);
                }
            };

            stageB(0); CP_COMMIT();
            stageB(1); CP_COMMIT();
            for (int ck = 0; ck < 16; ++ck) {
                if (ck + 2 < 16) { stageB(ck + 2); CP_COMMIT(); }
                if (ck <= 13)      { CP_WAIT(2); }
                else if (ck == 14) { CP_WAIT(1); }
                else               { CP_WAIT(0); }
                __syncthreads();

                uint32_t auh = sb + (ck & 3) * 32768, aul = auh + 16384;
                uint32_t buh = sb + 131072 + (ck & 3) * 16384, bul = buh + 8192;
                #pragma unroll
                for (int g = 0; g < 4; ++g) {
                    uint32_t baddr = (g >> 1) * 4096 + (cs * 8 + (lane & 7)) * 128 +
                                     (g & 1) * 64 + (lane >> 3) * 16;
                    uint32_t bh[4], bl_[4];
                    ldsm_x4(bh,  buh + SWZ(baddr));
                    ldsm_x4(bl_, bul + SWZ(baddr));
                    #pragma unroll
                    for (int sh = 0; sh < 2; ++sh) {
                        int s = g * 2 + sh;
                        uint32_t aaddr = (s >> 2) * 8192 + (rs * 16 + (lane & 15)) * 128 +
                                         (s & 3) * 32 + (lane >> 4) * 16;
                        uint32_t ah[4], al_[4];
                        ldsm_x4(ah,  auh + SWZ(aaddr));
                        ldsm_x4(al_, aul + SWZ(aaddr));
                        mma_bf16(dhh, ah,  bh[2 * sh],  bh[2 * sh + 1]);
                        mma_bf16(dhl, ah,  bl_[2 * sh], bl_[2 * sh + 1]);
                        mma_bf16(dlh, al_, bh[2 * sh],  bh[2 * sh + 1]);
                    }
                }
            }
            __syncthreads();   // all warps done with last buffers before writeback/barrier
            int m = c * 64 + rs * 16 + (lane >> 2);
            int n = cs * 8 + (lane & 3) * 2;
            g_ugemm[n][m]         = dhh[0] + dhl[0] + dlh[0];
            g_ugemm[n + 1][m]     = dhh[1] + dhl[1] + dlh[1];
            g_ugemm[n][m + 8]     = dhh[2] + dhl[2] + dlh[2];
            g_ugemm[n + 1][m + 8] = dhh[3] + dhl[3] + dlh[3];
        }
        grid_sync();

        // ===== C: serial layer chain, W-GEMM on mma.sync (3 chains) =====
        #pragma unroll
        for (int l = 0; l < 4; ++l) {
            const char* isrc = (l == 0) ? (g_xpimg + (size_t)t * 65536)
                                        : (g_hinimg + (size_t)(l - 1) * 65536);
            #pragma unroll
            for (int i = 0; i < 8; ++i) {
                int idx = i * 512 + tid;
                cp16(sb + idx * 16, isrc + idx * 16);
            }
            if (l == 0) {
                const char* wsrc = g_Wimg + ((size_t)c * 2) * 16384;
                #pragma unroll
                for (int i = 0; i < 4; ++i) {
                    int idx = i * 512 + tid;
                    cp16(sb + 65536 + idx * 16, wsrc + idx * 16);
                }
            }
            CP_COMMIT();
            if (l < 3) {
                const char* wsrc = g_Wimg + ((size_t)((l + 1) * 128 + c) * 2) * 16384;
                uint32_t wdst = sb + 65536 + ((l + 1) & 1) * 32768;
                #pragma unroll
                for (int i = 0; i < 4; ++i) {
                    int idx = i * 512 + tid;
                    cp16(wdst + idx * 16, wsrc + idx * 16);
                }
                CP_COMMIT();
            }

            // embedded A for layer l-1, step t+1 (overlapped with cp.async in flight)
            if (l >= 1 && t != TT - 1 && al == l - 1) do_A(t + 1);

            if (l < 3) { CP_WAIT(1); } else { CP_WAIT(0); }
            __syncthreads();

            float ug = g_ugemm[cb][l * G4 + crow];

            float dhh[4] = {0.f, 0.f, 0.f, 0.f};
            float dhl[4] = {0.f, 0.f, 0.f, 0.f};
            float dlh[4] = {0.f, 0.f, 0.f, 0.f};
            uint32_t wh = sb + 65536 + (l & 1) * 32768, wl = wh + 16384;
            uint32_t ih = sb, il = sb + 32768;
            #pragma unroll
            for (int gg = 0; gg < 4; ++gg) {
                uint32_t baddr = (ks * 2 + (gg >> 1)) * 4096 + (ns * 8 + (lane & 7)) * 128 +
                                 (gg & 1) * 64 + (lane >> 3) * 16;
                uint32_t bh[4], bl_[4];
                ldsm_x4(bh,  ih + SWZ(baddr));
                ldsm_x4(bl_, il + SWZ(baddr));
                #pragma unroll
                for (int jh = 0; jh < 2; ++jh) {
                    int s = ks * 8 + gg * 2 + jh;
                    uint32_t aaddr = (s >> 2) * 2048 + (lane & 15) * 128 +
                                     (s & 3) * 32 + (lane >> 4) * 16;
                    uint32_t ah[4], al_[4];
                    ldsm_x4(ah,  wh + SWZ(aaddr));
                    ldsm_x4(al_, wl + SWZ(aaddr));
                    mma_bf16(dhh, ah,  bh[2 * jh],  bh[2 * jh + 1]);
                    mma_bf16(dhl, ah,  bl_[2 * jh], bl_[2 * jh + 1]);
                    mma_bf16(dlh, al_, bh[2 * jh],  bh[2 * jh + 1]);
                }
            }
            {
                int m0 = lane >> 2, n0 = ns * 8 + (lane & 3) * 2;
                red[ks][m0][n0]         = dhh[0] + dhl[0] + dlh[0];
                red[ks][m0][n0 + 1]     = dhh[1] + dhl[1] + dlh[1];
                red[ks][m0 + 8][n0]     = dhh[2] + dhl[2] + dlh[2];
                red[ks][m0 + 8][n0 + 1] = dhh[3] + dhl[3] + dlh[3];
            }
            __syncthreads();

            float a = red[0][r16][cb] + red[1][r16][cb] +
                      red[2][r16][cb] + red[3][r16][cb] + ug;
            float act = (q == 2) ? tanh_f(a) : sigm(a);
            sm_g[r16][cb] = act;
            __syncthreads();
            if (q == 0) {
                float gf  = sm_g[4 + ms][cb];
                float gg_ = sm_g[8 + ms][cb];
                float go  = sm_g[12 + ms][cb];
                float cold = g_c[l][cb][mg];
                float cn = gf * cold + act * gg_;
                float hy = go * tanh_f(cn);
                g_c[l][cb][mg] = cn;
                g_h[l][cb][mg] = hy;
                if (l < 3) {
                    float hv = hy * mwv[l];
                    __nv_bfloat16 hb = __float2bfloat16(hv);
                    __nv_bfloat16 lb = __float2bfloat16(hv - __bfloat162float(hb));
                    int seg = mg >> 3;
                    unsigned byte = SWZ((unsigned)((cb >> 3) * 1024 + (seg >> 3) * 4096 +
                                                   (cb & 7) * 128 + (seg & 7) * 16 + (mg & 7) * 2));
                    char* base = g_hinimg + (size_t)l * 65536;
                    *(__nv_bfloat16*)(base + byte) = hb;
                    *(__nv_bfloat16*)(base + 32768 + byte) = lb;
                }
            }
            grid_sync();
        }
    }

    const float* hp = &g_h[0][0][0];
    const float* cp = &g_c[0][0][0];
    for (int idx = c * NTHR + tid; idx < L * BATCH * H; idx += NCTA * NTHR) {
        out_h[idx] = hp[idx];
        out_c[idx] = cp[idx];
    }
}

// ---- launch ----
extern "C" void kernel_launch(void* const* d_in, const int* in_sizes, int n_in,
                              void* d_out, int out_size)
{
    const float* x      = (const float*)d_in[0];
    const float* lin_w  = (const float*)d_in[1];
    const float* lin_b  = (const float*)d_in[2];
    const float* W      = (const float*)d_in[3];
    const float* U      = (const float*)d_in[4];
    const float* G      = (const float*)d_in[5];
    const float* mask_u = (const float*)d_in[6];
    const float* mask_w = (const float*)d_in[7];
    const float* h0     = (const float*)d_in[8];
    const float* c0     = (const float*)d_in[9];
    float* out = (float*)d_out;
    (void)in_sizes; (void)n_in; (void)out_size;

    prep_all<<<2048 + 512, 256>>>(U, W);
    xp_kernel<<<(TT * BATCH) / 16, 256>>>(x, lin_w, lin_b, mask_w);
    init_hc<<<64, 256>>>(h0, c0);

    cudaFuncSetAttribute(rnn_kernel, cudaFuncAttributeMaxDynamicSharedMemorySize, SMEM_DYN);
    rnn_kernel<<<NCTA, NTHR, SMEM_DYN>>>(G, mask_u, mask_w, out);
}

// round 11
// speedup vs baseline: 1.5491x; 1.2038x over previous
#include <cuda_runtime.h>
#include <cuda_fp16.h>
#include <math.h>
#include <stdint.h>

#define L     4
#define H     512
#define BATCH 32
#define TT    1024
#define G4    2048
#define LH    2048
#define JTOT  8192
#define NCTA  128
#define NTHR  512

#define SWZ(o) ((unsigned)(o) ^ (((unsigned)(o) >> 3) & 0x70u))

// ---- PTX helpers (base-target features only) ----
__device__ __forceinline__ uint32_t smem_u32(const void* p) {
    uint32_t a;
    asm("{ .reg .u64 t; cvta.to.shared.u64 t, %1; cvt.u32.u64 %0, t; }" : "=r"(a) : "l"(p));
    return a;
}
__device__ __forceinline__ void cp16(uint32_t dst, const void* src) {
    asm volatile("cp.async.cg.shared.global [%0], [%1], 16;" :: "r"(dst), "l"(src) : "memory");
}
#define CP_COMMIT() asm volatile("cp.async.commit_group;" ::: "memory")
#define CP_WAIT(n)  asm volatile("cp.async.wait_group %0;" :: "n"(n) : "memory")

__device__ __forceinline__ void ldsm_x4(uint32_t* r, uint32_t addr) {
    asm volatile("ldmatrix.sync.aligned.m8n8.x4.shared.b16 {%0,%1,%2,%3}, [%4];"
        : "=r"(r[0]), "=r"(r[1]), "=r"(r[2]), "=r"(r[3]) : "r"(addr));
}
__device__ __forceinline__ void mma_f16(float* d, const uint32_t* a, uint32_t b0, uint32_t b1) {
    asm volatile("mma.sync.aligned.m16n8k16.row.col.f32.f16.f16.f32 "
        "{%0,%1,%2,%3}, {%4,%5,%6,%7}, {%8,%9}, {%0,%1,%2,%3};"
        : "+f"(d[0]), "+f"(d[1]), "+f"(d[2]), "+f"(d[3])
        : "r"(a[0]), "r"(a[1]), "r"(a[2]), "r"(a[3]), "r"(b0), "r"(b1));
}
__device__ __forceinline__ void wait_cnt(const unsigned* p, unsigned target) {
    unsigned v;
    do {
        asm volatile("ld.acquire.gpu.global.u32 %0, [%1];" : "=r"(v) : "l"(p) : "memory");
    } while (v < target);
}
__device__ __forceinline__ float sigm(float x) { return 1.f / (1.f + __expf(-x)); }
__device__ __forceinline__ float tanh_f(float x) { return 1.f - 2.f / (1.f + __expf(2.f * x)); }

// ---- static device scratch ----
__device__ __align__(16) char g_Uimg[(size_t)128 * 16 * 16384];      // [c][chunk] 16KB fp16
__device__ __align__(16) char g_Wimg[(size_t)4 * 128 * 16384];       // [l][c] 16KB fp16
__device__ __align__(16) char g_xpimg[(size_t)TT * 2 * 32768];       // [t][hi/lo] fp16
__device__ __align__(16) char g_hinimg[(size_t)3 * 2 * 32768];       // [l][hi/lo]
__device__ __align__(16) char g_hximg[(size_t)16 * 16384];           // [chunk] hi@0 lo@8192
__device__ float g_h[L][BATCH][H];
__device__ float g_c[L][BATCH][H];
__device__ float g_ugemm[BATCH][JTOT];
__device__ unsigned g_cntA3;
__device__ unsigned g_cnt = 0;
__device__ volatile unsigned g_gen = 0;

// ---- software grid barrier (R6-proven) ----
__device__ __forceinline__ void grid_sync()
{
    __syncthreads();
    if (threadIdx.x == 0) {
        unsigned g = g_gen;
        __threadfence();
        if (atomicAdd(&g_cnt, 1u) == NCTA - 1u) {
            g_cnt = 0;
            __threadfence();
            g_gen = g + 1u;
        } else {
            while (g_gen == g) { }
        }
        __threadfence();
    }
    __syncthreads();
}

// ---- prep kernels (merged: U blocks 0..2047, W blocks 2048..2559) ----
__global__ void prep_all(const float* __restrict__ U, const float* __restrict__ W)
{
    if (blockIdx.x < 2048) {
        int blk = blockIdx.x;                 // c*16 + chunk
        int c = blk >> 4, chunk = blk & 15;
        char* dst = g_Uimg + (size_t)blk * 16384;
        for (int i = threadIdx.x; i < 1024; i += 256) {
            int r = i >> 4, s8 = i & 15;
            const float* src = U + ((size_t)(c * 64 + r)) * LH + chunk * 128 + s8 * 8;
            __half hv[8];
            #pragma unroll
            for (int j = 0; j < 8; ++j) hv[j] = __float2half_rn(src[j]);
            unsigned byte = SWZ((unsigned)((r >> 3) * 1024 + (s8 >> 3) * 8192 +
                                           (r & 7) * 128 + (s8 & 7) * 16));
            *(uint4*)(dst + byte) = *(uint4*)hv;
        }
    } else {
        int blk = blockIdx.x - 2048;          // l*128 + c
        int l = blk >> 7, c = blk & 127;
        char* dst = g_Wimg + (size_t)blk * 16384;
        for (int i = threadIdx.x; i < 1024; i += 256) {
            int r = i >> 6, s8 = i & 63;
            int q = r >> 2, ms = r & 3;
            int wrow = q * 512 + c * 4 + ms;
            const float* src = W + ((size_t)(l * G4 + wrow)) * H + s8 * 8;
            __half hv[8];
            #pragma unroll
            for (int j = 0; j < 8; ++j) hv[j] = __float2half_rn(src[j]);
            unsigned byte = SWZ((unsigned)((r >> 3) * 1024 + (s8 >> 3) * 2048 +
                                           (r & 7) * 128 + (s8 & 7) * 16));
            *(uint4*)(dst + byte) = *(uint4*)hv;
        }
    }
}

__global__ void xp_kernel(const float* __restrict__ x,
                          const float* __restrict__ lin_w,
                          const float* __restrict__ lin_b,
                          const float* __restrict__ mask_w)
{
    __shared__ float xs[16][128];
    int tb0 = blockIdx.x * 16;
    int tid = threadIdx.x;
    #pragma unroll
    for (int r = 0; r < 8; ++r) {
        int e = r * 256 + tid;
        xs[e >> 7][e & 127] = x[(size_t)(tb0 + (e >> 7)) * 128 + (e & 127)];
    }
    __syncthreads();
    int h0 = tid, h1 = tid + 256;
    const float* w0 = lin_w + (size_t)h0 * 128;
    const float* w1 = lin_w + (size_t)h1 * 128;
    float acc0[16], acc1[16];
    #pragma unroll
    for (int p = 0; p < 16; ++p) { acc0[p] = 0.f; acc1[p] = 0.f; }
    for (int i = 0; i < 128; i += 4) {
        float4 a = *(const float4*)(w0 + i);
        float4 b = *(const float4*)(w1 + i);
        #pragma unroll
        for (int p = 0; p < 16; ++p) {
            float4 xv = *(const float4*)&xs[p][i];
            acc0[p] += a.x * xv.x + a.y * xv.y + a.z * xv.z + a.w * xv.w;
            acc1[p] += b.x * xv.x + b.y * xv.y + b.z * xv.z + b.w * xv.w;
        }
    }
    float b0 = lin_b[h0], b1 = lin_b[h1];
    #pragma unroll
    for (int p = 0; p < 16; ++p) {
        int tb = tb0 + p;
        int tt = tb >> 5, bb = tb & 31;
        char* base = g_xpimg + (size_t)tt * 65536;
        #pragma unroll
        for (int cc = 0; cc < 2; ++cc) {
            int hh = cc ? h1 : h0;
            float v = ((cc ? acc1[p] : acc0[p]) + (cc ? b1 : b0)) *
                      mask_w[(size_t)bb * H + hh];
            __half hb = __float2half_rn(v);
            __half lb = __float2half_rn(v - __half2float(hb));
            int seg = hh >> 3;
            unsigned byte = SWZ((unsigned)((bb >> 3) * 1024 + (seg >> 3) * 4096 +
                                           (bb & 7) * 128 + (seg & 7) * 16 + (hh & 7) * 2));
            *(__half*)(base + byte) = hb;
            *(__half*)(base + 32768 + byte) = lb;
        }
    }
}

__global__ void init_hc(const float* __restrict__ h0, const float* __restrict__ c0)
{
    if (blockIdx.x == 0 && threadIdx.x == 0) g_cntA3 = 0;
    float* hp = &g_h[0][0][0];
    float* cp = &g_c[0][0][0];
    for (int i = blockIdx.x * blockDim.x + threadIdx.x; i < L * BATCH * H;
         i += gridDim.x * blockDim.x)
        { hp[i] = h0[i]; cp[i] = c0[i]; }
}

// ---- persistent kernel ----
// dyn SMEM: Ubuf 4x16K @0..64K ; hxbuf 4x16K @65536..131072 ; W resident 4x16K @131072..196608
// C-phase: inp 64K @0..64K (reuses Ubuf region, time-separated)
#define SMEM_DYN (196608 + 1024)

__global__ void __launch_bounds__(NTHR, 1)
rnn_kernel(const float* __restrict__ G,
           const float* __restrict__ mask_u,
           const float* __restrict__ mask_w,
           float* __restrict__ out)
{
    extern __shared__ char smc_raw[];
    __shared__ float redA[16];
    __shared__ float ghA;
    __shared__ float sm_g[16][33];
    __shared__ float red[4][16][33];

    const int c    = blockIdx.x;
    const int tid  = threadIdx.x;
    const int wid  = tid >> 5;
    const int lane = tid & 31;

    uint32_t sbr = smem_u32(smc_raw);
    uint32_t sb  = (sbr + 1023u) & ~1023u;

    // A: CTA = (layer, batch)
    const int al  = c & 3;
    const int abt = c >> 2;
    // B: warp = 4 J strips x 4 batch strips
    const int rs = wid >> 2;
    const int cs = wid & 3;
    // C: warp = (K split, batch strip); thread = (row r16, batch cb)
    const int ks = wid >> 2;
    const int ns = wid & 3;
    const int cb   = wid * 2 + (lane & 1);
    const int r16  = lane >> 1;
    const int q    = r16 >> 2;
    const int ms   = r16 & 3;
    const int mg   = c * 4 + ms;
    const int crow = q * 512 + mg;

    // hoisted per-thread constants
    const float Gv   = G[al * H + tid];
    const float muv  = mask_u[((size_t)(al * BATCH + abt)) * H + tid];
    float mwv[3];
    #pragma unroll
    for (int l = 0; l < 3; ++l)
        mwv[l] = mask_w[((size_t)((l + 1) * BATCH + cb)) * H + mg];

    float* out_h = out;
    float* out_c = out + L * BATCH * H;
    float* out_g = out + 2 * L * BATCH * H;

    // A work: gate + gated-masked hidden -> hx fp16 hi/lo image
    auto do_A = [&](int t_out) {
        float hm = g_h[al][abt][tid] * muv;
        float s  = hm * Gv;
        #pragma unroll
        for (int o = 16; o; o >>= 1) s += __shfl_xor_sync(~0u, s, o);
        if (lane == 0) redA[wid] = s;
        __syncthreads();
        if (tid == 0) {
            float ss = 0.f;
            #pragma unroll
            for (int r = 0; r < 16; ++r) ss += redA[r];
            float gh = sigm(ss);
            ghA = gh;
            out_g[(size_t)(al * BATCH + abt) * TT + t_out] = gh;
        }
        __syncthreads();
        float v = ghA * hm;
        __half hb = __float2half_rn(v);
        __half lb = __float2half_rn(v - __half2float(hb));
        int kg = al * 512 + tid;
        int chunk = kg >> 7, kl = kg & 127, seg = kl >> 3;
        unsigned byte = SWZ((unsigned)((abt >> 3) * 1024 + (seg >> 3) * 4096 +
                                       (abt & 7) * 128 + (seg & 7) * 16 + (kl & 7) * 2));
        char* base = g_hximg + (size_t)chunk * 16384;
        *(__half*)(base + byte) = hb;
        *(__half*)(base + 8192 + byte) = lb;
        if (al == 3) {
            __syncthreads();
            if (tid == 0) {
                __threadfence();
                atomicAdd(&g_cntA3, 1u);
            }
        }
    };

    // load resident W (all 4 layers, 64KB) into SMEM @131072
    {
        const char* wsrc = g_Wimg;
        #pragma unroll
        for (int i = 0; i < 8; ++i) {
            int idx = i * 512 + tid;               // 0..4095 (layer = idx>>10)
            int l = idx >> 10, off = idx & 1023;
            cp16(sb + 131072 + l * 16384 + off * 16,
                 wsrc + ((size_t)(l * 128 + c)) * 16384 + off * 16);
        }
        CP_COMMIT();
    }

    // peel: A for t=0, drain W load, then one grid sync before B(0)
    do_A(0);
    CP_WAIT(0);
    grid_sync();

    for (int t = 0; t < TT; ++t) {
        // layer-3 A for step t
        if (t >= 1 && al == 3) do_A(t);

        // ===== B: U-GEMM (fp16, 2 terms), 4-buffer pipeline, 1 sync per chunk =====
        {
            float dh[4] = {0.f, 0.f, 0.f, 0.f};
            float dl[4] = {0.f, 0.f, 0.f, 0.f};

            auto stageB = [&](int ck) {
                if (ck == 12) wait_cnt(&g_cntA3, 32u * (unsigned)(t + 1));
                int buf = ck & 3;
                const char* us = g_Uimg + (size_t)(c * 16 + ck) * 16384;
                #pragma unroll
                for (int i = 0; i < 2; ++i) {
                    int idx = i * 512 + tid;
                    cp16(sb + buf * 16384 + idx * 16, us + idx * 16);
                }
                const char* hs = g_hximg + (size_t)ck * 16384;
                #pragma unroll
                for (int i = 0; i < 2; ++i) {
                    int idx = i * 512 + tid;
                    cp16(sb + 65536 + buf * 16384 + idx * 16, hs + idx * 16);
                }
            };

            stageB(0); CP_COMMIT();
            stageB(1); CP_COMMIT();
            for (int ck = 0; ck < 16; ++ck) {
                if (ck + 2 < 16) { stageB(ck + 2); CP_COMMIT(); }
                if (ck <= 13)      { CP_WAIT(2); }
                else if (ck == 14) { CP_WAIT(1); }
                else               { CP_WAIT(0); }
                __syncthreads();

                uint32_t au  = sb + (ck & 3) * 16384;
                uint32_t buh = sb + 65536 + (ck & 3) * 16384, bul = buh + 8192;
                #pragma unroll
                for (int g = 0; g < 4; ++g) {
                    uint32_t baddr = (g >> 1) * 4096 + (cs * 8 + (lane & 7)) * 128 +
                                     (g & 1) * 64 + (lane >> 3) * 16;
                    uint32_t bh[4], bl_[4];
                    ldsm_x4(bh,  buh + SWZ(baddr));
                    ldsm_x4(bl_, bul + SWZ(baddr));
                    #pragma unroll
                    for (int sh = 0; sh < 2; ++sh) {
                        int s = g * 2 + sh;
                        uint32_t aaddr = (s >> 2) * 8192 + (rs * 16 + (lane & 15)) * 128 +
                                         (s & 3) * 32 + (lane >> 4) * 16;
                        uint32_t ah[4];
                        ldsm_x4(ah, au + SWZ(aaddr));
                        mma_f16(dh, ah, bh[2 * sh],  bh[2 * sh + 1]);
                        mma_f16(dl, ah, bl_[2 * sh], bl_[2 * sh + 1]);
                    }
                }
            }
            __syncthreads();
            int m = c * 64 + rs * 16 + (lane >> 2);
            int n = cs * 8 + (lane & 3) * 2;
            g_ugemm[n][m]         = dh[0] + dl[0];
            g_ugemm[n + 1][m]     = dh[1] + dl[1];
            g_ugemm[n][m + 8]     = dh[2] + dl[2];
            g_ugemm[n + 1][m + 8] = dh[3] + dl[3];
        }
        grid_sync();

        // ===== C: serial layer chain, W resident in SMEM =====
        #pragma unroll
        for (int l = 0; l < 4; ++l) {
            const char* isrc = (l == 0) ? (g_xpimg + (size_t)t * 65536)
                                        : (g_hinimg + (size_t)(l - 1) * 65536);
            #pragma unroll
            for (int i = 0; i < 8; ++i) {
                int idx = i * 512 + tid;
                cp16(sb + idx * 16, isrc + idx * 16);
            }
            CP_COMMIT();

            // embedded A for layer l-1, step t+1 (overlapped with cp.async)
            if (l >= 1 && t != TT - 1 && al == l - 1) do_A(t + 1);

            CP_WAIT(0);
            __syncthreads();

            float ug = g_ugemm[cb][l * G4 + crow];

            float ddh[4] = {0.f, 0.f, 0.f, 0.f};
            float ddl[4] = {0.f, 0.f, 0.f, 0.f};
            uint32_t wres = sb + 131072 + l * 16384;
            uint32_t ih = sb, il = sb + 32768;
            #pragma unroll
            for (int gg = 0; gg < 4; ++gg) {
                uint32_t baddr = (ks * 2 + (gg >> 1)) * 4096 + (ns * 8 + (lane & 7)) * 128 +
                                 (gg & 1) * 64 + (lane >> 3) * 16;
                uint32_t bh[4], bl_[4];
                ldsm_x4(bh,  ih + SWZ(baddr));
                ldsm_x4(bl_, il + SWZ(baddr));
                #pragma unroll
                for (int jh = 0; jh < 2; ++jh) {
                    int s = ks * 8 + gg * 2 + jh;
                    uint32_t aaddr = (s >> 2) * 2048 + (lane & 15) * 128 +
                                     (s & 3) * 32 + (lane >> 4) * 16;
                    uint32_t ah[4];
                    ldsm_x4(ah, wres + SWZ(aaddr));
                    mma_f16(ddh, ah, bh[2 * jh],  bh[2 * jh + 1]);
                    mma_f16(ddl, ah, bl_[2 * jh], bl_[2 * jh + 1]);
                }
            }
            {
                int m0 = lane >> 2, n0 = ns * 8 + (lane & 3) * 2;
                red[ks][m0][n0]         = ddh[0] + ddl[0];
                red[ks][m0][n0 + 1]     = ddh[1] + ddl[1];
                red[ks][m0 + 8][n0]     = ddh[2] + ddl[2];
                red[ks][m0 + 8][n0 + 1] = ddh[3] + ddl[3];
            }
            __syncthreads();

            float a = red[0][r16][cb] + red[1][r16][cb] +
                      red[2][r16][cb] + red[3][r16][cb] + ug;
            float act = (q == 2) ? tanh_f(a) : sigm(a);
            sm_g[r16][cb] = act;
            __syncthreads();
            if (q == 0) {
                float gf  = sm_g[4 + ms][cb];
                float gg_ = sm_g[8 + ms][cb];
                float go  = sm_g[12 + ms][cb];
                float cold = g_c[l][cb][mg];
                float cn = gf * cold + act * gg_;
                float hy = go * tanh_f(cn);
                g_c[l][cb][mg] = cn;
                g_h[l][cb][mg] = hy;
                if (l < 3) {
                    float hv = hy * mwv[l];
                    __half hb = __float2half_rn(hv);
                    __half lb = __float2half_rn(hv - __half2float(hb));
                    int seg = mg >> 3;
                    unsigned byte = SWZ((unsigned)((cb >> 3) * 1024 + (seg >> 3) * 4096 +
                                                   (cb & 7) * 128 + (seg & 7) * 16 + (mg & 7) * 2));
                    char* base = g_hinimg + (size_t)l * 65536;
                    *(__half*)(base + byte) = hb;
                    *(__half*)(base + 32768 + byte) = lb;
                }
            }
            grid_sync();
        }
    }

    const float* hp = &g_h[0][0][0];
    const float* cp = &g_c[0][0][0];
    for (int idx = c * NTHR + tid; idx < L * BATCH * H; idx += NCTA * NTHR) {
        out_h[idx] = hp[idx];
        out_c[idx] = cp[idx];
    }
}

// ---- launch ----
extern "C" void kernel_launch(void* const* d_in, const int* in_sizes, int n_in,
                              void* d_out, int out_size)
{
    const float* x      = (const float*)d_in[0];
    const float* lin_w  = (const float*)d_in[1];
    const float* lin_b  = (const float*)d_in[2];
    const float* W      = (const float*)d_in[3];
    const float* U      = (const float*)d_in[4];
    const float* G      = (const float*)d_in[5];
    const float* mask_u = (const float*)d_in[6];
    const float* mask_w = (const float*)d_in[7];
    const float* h0     = (const float*)d_in[8];
    const float* c0     = (const float*)d_in[9];
    float* out = (float*)d_out;
    (void)in_sizes; (void)n_in; (void)out_size;

    prep_all<<<2048 + 512, 256>>>(U, W);
    xp_kernel<<<(TT * BATCH) / 16, 256>>>(x, lin_w, lin_b, mask_w);
    init_hc<<<64, 256>>>(h0, c0);

    cudaFuncSetAttribute(rnn_kernel, cudaFuncAttributeMaxDynamicSharedMemorySize, SMEM_DYN);
    rnn_kernel<<<NCTA, NTHR, SMEM_DYN>>>(G, mask_u, mask_w, out);
}